// round 6
// baseline (speedup 1.0000x reference)
#include <cuda_runtime.h>

#define NN   10000
#define DEG  32
#define DIM  256
#define NHEADS 8
#define HDIM 32
#define NE   (NN*DEG)

// Scratch for projected Q/K/V (no cudaMalloc allowed)
__device__ float g_Q[NN * DIM];
__device__ float g_K[NN * DIM];
__device__ float g_V[NN * DIM];

// ---------------------------------------------------------------------------
// Kernel 1: Q/K/V projections.  C = x @ W, W selected by blockIdx.z.
// 128x64 tile, BK=16, 128 threads, 8x8 micro-tile (split columns: tx*4 and
// 32+tx*4 -> conflict-free Bs reads).
// ---------------------------------------------------------------------------
__global__ __launch_bounds__(128) void qkv_kernel(
    const float* __restrict__ x,
    const float* __restrict__ WQ,
    const float* __restrict__ WK,
    const float* __restrict__ WV)
{
    const float* W = (blockIdx.z == 0) ? WQ : (blockIdx.z == 1) ? WK : WV;
    float* C       = (blockIdx.z == 0) ? g_Q : (blockIdx.z == 1) ? g_K : g_V;

    __shared__ float As[16][132];   // [k][m], padded
    __shared__ float Bs[16][68];    // [k][n]

    const int tid = threadIdx.x;
    const int tx = tid & 7, ty = tid >> 3;     // ty in [0,16)
    const int m0 = blockIdx.x * 128, n0 = blockIdx.y * 64;

    float acc[8][8] = {};

    for (int k0 = 0; k0 < DIM; k0 += 16) {
        // x tile: 128 rows x 16 cols, transposed store
        #pragma unroll
        for (int l = 0; l < 4; l++) {
            int idx = tid + l * 128;
            int r = idx >> 2;
            int c = (idx & 3) << 2;
            float4 v = make_float4(0.f, 0.f, 0.f, 0.f);
            int gm = m0 + r;
            if (gm < NN) v = *(const float4*)(x + (size_t)gm * DIM + k0 + c);
            As[c + 0][r] = v.x; As[c + 1][r] = v.y;
            As[c + 2][r] = v.z; As[c + 3][r] = v.w;
        }
        // W tile: 16 rows x 64 cols
        #pragma unroll
        for (int l = 0; l < 2; l++) {
            int idx = tid + l * 128;
            int wr = idx >> 4, wc = (idx & 15) << 2;
            *(float4*)&Bs[wr][wc] = *(const float4*)(W + (size_t)(k0 + wr) * DIM + n0 + wc);
        }
        __syncthreads();

        #pragma unroll 8
        for (int k = 0; k < 16; k++) {
            float a[8], b[8];
            *(float4*)&a[0] = *(float4*)&As[k][ty << 3];
            *(float4*)&a[4] = *(float4*)&As[k][(ty << 3) + 4];
            *(float4*)&b[0] = *(float4*)&Bs[k][tx << 2];
            *(float4*)&b[4] = *(float4*)&Bs[k][32 + (tx << 2)];
            #pragma unroll
            for (int r = 0; r < 8; r++)
                #pragma unroll
                for (int j = 0; j < 8; j++)
                    acc[r][j] += a[r] * b[j];
        }
        __syncthreads();
    }

    #pragma unroll
    for (int r = 0; r < 8; r++) {
        int gm = m0 + (ty << 3) + r;
        if (gm < NN) {
            *(float4*)(C + (size_t)gm * DIM + n0 + (tx << 2)) =
                make_float4(acc[r][0], acc[r][1], acc[r][2], acc[r][3]);
            *(float4*)(C + (size_t)gm * DIM + n0 + 32 + (tx << 2)) =
                make_float4(acc[r][4], acc[r][5], acc[r][6], acc[r][7]);
        }
    }
}

// ---------------------------------------------------------------------------
// Kernel 2: fused edge pipeline.
// One block = 128 edges (4 nodes) x 2 heads (64 cols), 128 threads.
//   Phase 1: E1 tile GEMM (8x8 micro, split cols) + fused E2 dots (both heads).
//   Phase 2: score = sum_k E1 * K[nbr] * Q[node] (+E2), clip; 8-lane reduce.
//   Phase 3: softmax over deg=32, warp per node, loop over 2 heads.
//   Phase 4: out = attn @ V[nbr]; coalesced V row reads, 2 cols per thread.
// ---------------------------------------------------------------------------
__global__ __launch_bounds__(128) void edge_kernel(
    const float* __restrict__ ea,
    const int* __restrict__ eidx,       // edge_index row 0 = neighbors (int32)
    const float* __restrict__ WE1,
    const float* __restrict__ WE2,
    const float* __restrict__ bE2,
    float* __restrict__ out)
{
    const int hg   = blockIdx.x;        // head-group 0..3 (heads 2hg, 2hg+1)
    const int tile = blockIdx.y;        // 0..2499
    const int e0   = tile * 128;
    const int ncol0 = hg * 64;

    __shared__ float As[16][132];       // ea chunk [c][e]
    __shared__ float Bs[16][68];        // WE1 chunk [c][n]
    __shared__ float W2s[16][2];
    __shared__ float sc[2][128];        // scores -> attn
    __shared__ float e2s[2][128];
    __shared__ int   nb[128];

    const int tid = threadIdx.x;
    const int tx = tid & 7, ty = tid >> 3;  // ty in [0,16)

    nb[tid] = eidx[e0 + tid];

    float acc[8][8] = {};
    float e2a0 = 0.f, e2a1 = 0.f;

    for (int k0 = 0; k0 < DIM; k0 += 16) {
        // edge_attr tile: 128 x 16 (transposed into As)
        #pragma unroll
        for (int l = 0; l < 4; l++) {
            int idx = tid + l * 128;
            int r = idx >> 2;
            int c = (idx & 3) << 2;
            float4 v = *(const float4*)(ea + (size_t)(e0 + r) * DIM + k0 + c);
            As[c + 0][r] = v.x; As[c + 1][r] = v.y;
            As[c + 2][r] = v.z; As[c + 3][r] = v.w;
        }
        // WE1 tile: 16 x 64
        #pragma unroll
        for (int l = 0; l < 2; l++) {
            int idx = tid + l * 128;
            int wr = idx >> 4, wc = (idx & 15) << 2;
            *(float4*)&Bs[wr][wc] = *(const float4*)(WE1 + (size_t)(k0 + wr) * DIM + ncol0 + wc);
        }
        // WE2 tile: 16 x 2
        if (tid < 32) {
            int wr = tid >> 1, wc = tid & 1;
            W2s[wr][wc] = WE2[(k0 + wr) * NHEADS + hg * 2 + wc];
        }
        __syncthreads();

        #pragma unroll 8
        for (int k = 0; k < 16; k++) {
            float a[8], b[8];
            *(float4*)&a[0] = *(float4*)&As[k][ty << 3];
            *(float4*)&a[4] = *(float4*)&As[k][(ty << 3) + 4];
            *(float4*)&b[0] = *(float4*)&Bs[k][tx << 2];
            *(float4*)&b[4] = *(float4*)&Bs[k][32 + (tx << 2)];
            #pragma unroll
            for (int r = 0; r < 8; r++)
                #pragma unroll
                for (int j = 0; j < 8; j++)
                    acc[r][j] += a[r] * b[j];
            // fused E2: edge = tid, both heads
            float ae = As[k][tid];
            e2a0 += ae * W2s[k][0];
            e2a1 += ae * W2s[k][1];
        }
        __syncthreads();
    }

    e2s[0][tid] = e2a0 + bE2[hg * 2 + 0];
    e2s[1][tid] = e2a1 + bE2[hg * 2 + 1];
    __syncthreads();

    // ---- Phase 2: scores --------------------------------------------------
    // Thread covers edges e = ty*8 + r (8 | 32 -> one node per thread-row
    // group), head0 cols ncol0+tx*4+j (acc[.][0..3]), head1 cols
    // ncol0+32+tx*4+j (acc[.][4..7]). Reduce over the 8 tx lanes.
    const int node_l = ty >> 2;
    const int node   = tile * 4 + node_l;
    const float4 q4a = *(const float4*)(g_Q + (size_t)node * DIM + ncol0 + (tx << 2));
    const float4 q4b = *(const float4*)(g_Q + (size_t)node * DIM + ncol0 + 32 + (tx << 2));

    #pragma unroll
    for (int r = 0; r < 8; r++) {
        int e = (ty << 3) + r;
        int m = nb[e];
        float4 k4a = *(const float4*)(g_K + (size_t)m * DIM + ncol0 + (tx << 2));
        float4 k4b = *(const float4*)(g_K + (size_t)m * DIM + ncol0 + 32 + (tx << 2));
        float p0 = acc[r][0] * k4a.x * q4a.x + acc[r][1] * k4a.y * q4a.y
                 + acc[r][2] * k4a.z * q4a.z + acc[r][3] * k4a.w * q4a.w;
        float p1 = acc[r][4] * k4b.x * q4b.x + acc[r][5] * k4b.y * q4b.y
                 + acc[r][6] * k4b.z * q4b.z + acc[r][7] * k4b.w * q4b.w;
        #pragma unroll
        for (int o = 1; o < 8; o <<= 1) {
            p0 += __shfl_xor_sync(0xffffffffu, p0, o);
            p1 += __shfl_xor_sync(0xffffffffu, p1, o);
        }
        if (tx == 0) {
            float s0 = p0 + e2s[0][e];
            float s1 = p1 + e2s[1][e];
            sc[0][e] = fminf(fmaxf(s0, -8.f), 8.f);
            sc[1][e] = fminf(fmaxf(s1, -8.f), 8.f);
        }
    }
    __syncthreads();

    // ---- Phase 3: softmax over deg=32, warp per node, 2 heads ------------
    {
        #pragma unroll
        for (int h = 0; h < 2; h++) {
            float s = sc[h][tid];           // warp w covers edges w*32..w*32+31
            float mx = s;
            #pragma unroll
            for (int o = 16; o; o >>= 1) mx = fmaxf(mx, __shfl_xor_sync(0xffffffffu, mx, o));
            float p = __expf(s - mx);
            float sum = p;
            #pragma unroll
            for (int o = 16; o; o >>= 1) sum += __shfl_xor_sync(0xffffffffu, sum, o);
            sc[h][tid] = p / sum;           // warp-local rewrite, safe
        }
    }
    __syncthreads();

    // ---- Phase 4: output -------------------------------------------------
    {
        const int i  = tid >> 5;            // local node
        const int kk = tid & 31;
        const int col0 = ncol0 + kk;
        float acc0 = 0.f, acc1 = 0.f;
        #pragma unroll 8
        for (int d = 0; d < 32; d++) {
            int e = i * 32 + d;
            const float* vr = g_V + (size_t)nb[e] * DIM + col0;
            acc0 += sc[0][e] * vr[0];
            acc1 += sc[1][e] * vr[32];
        }
        size_t row = (size_t)(tile * 4 + i) * DIM;
        out[row + col0]      = acc0;
        out[row + col0 + 32] = acc1;
    }
}

// ---------------------------------------------------------------------------
extern "C" void kernel_launch(void* const* d_in, const int* in_sizes, int n_in,
                              void* d_out, int out_size)
{
    const float* x   = (const float*)d_in[0];
    const int*   ei  = (const int*)d_in[1];     // int32 (JAX x64 disabled)
    const float* ea  = (const float*)d_in[2];
    const float* WQ  = (const float*)d_in[3];
    const float* WK  = (const float*)d_in[4];
    const float* WV  = (const float*)d_in[5];
    const float* WE1 = (const float*)d_in[6];
    const float* WE2 = (const float*)d_in[7];
    const float* bE2 = (const float*)d_in[8];
    float* out = (float*)d_out;

    qkv_kernel<<<dim3((NN + 127) / 128, DIM / 64, 3), 128>>>(x, WQ, WK, WV);
    edge_kernel<<<dim3(4, NE / 128), 128>>>(ea, ei, WE1, WE2, bE2, out);
}

// round 9
// speedup vs baseline: 1.6162x; 1.6162x over previous
#include <cuda_runtime.h>

#define NN   10000
#define DEG  32
#define DIM  256
#define NHEADS 8
#define HDIM 32
#define NE   (NN*DEG)

// Scratch for projected Q/K/V (no cudaMalloc allowed)
__device__ float g_Q[NN * DIM];
__device__ float g_K[NN * DIM];
__device__ float g_V[NN * DIM];

// ---------------------------------------------------------------------------
// Kernel 1: Q/K/V projections (R4 known-good).  C = x @ W, W by blockIdx.z.
// 64x64 tile, BK=16, 256 threads, 4x4 micro-tile.
// ---------------------------------------------------------------------------
__global__ __launch_bounds__(256) void qkv_kernel(
    const float* __restrict__ x,
    const float* __restrict__ WQ,
    const float* __restrict__ WK,
    const float* __restrict__ WV)
{
    const float* W = (blockIdx.z == 0) ? WQ : (blockIdx.z == 1) ? WK : WV;
    float* C       = (blockIdx.z == 0) ? g_Q : (blockIdx.z == 1) ? g_K : g_V;

    __shared__ float As[16][68];
    __shared__ float Bs[16][68];

    const int tid = threadIdx.x;
    const int tx = tid & 15, ty = tid >> 4;
    const int m0 = blockIdx.x * 64, n0 = blockIdx.y * 64;

    float acc[4][4] = {};

    for (int k0 = 0; k0 < DIM; k0 += 16) {
        {
            int r = tid >> 2;
            int c = (tid & 3) << 2;
            float4 v = make_float4(0.f, 0.f, 0.f, 0.f);
            int gm = m0 + r;
            if (gm < NN) v = *(const float4*)(x + (size_t)gm * DIM + k0 + c);
            As[c + 0][r] = v.x; As[c + 1][r] = v.y;
            As[c + 2][r] = v.z; As[c + 3][r] = v.w;
        }
        {
            int wr = tid >> 4, wc = (tid & 15) << 2;
            *(float4*)&Bs[wr][wc] = *(const float4*)(W + (size_t)(k0 + wr) * DIM + n0 + wc);
        }
        __syncthreads();

        #pragma unroll
        for (int k = 0; k < 16; k++) {
            float4 a = *(float4*)&As[k][ty << 2];
            float4 b = *(float4*)&Bs[k][tx << 2];
            acc[0][0] += a.x * b.x; acc[0][1] += a.x * b.y; acc[0][2] += a.x * b.z; acc[0][3] += a.x * b.w;
            acc[1][0] += a.y * b.x; acc[1][1] += a.y * b.y; acc[1][2] += a.y * b.z; acc[1][3] += a.y * b.w;
            acc[2][0] += a.z * b.x; acc[2][1] += a.z * b.y; acc[2][2] += a.z * b.z; acc[2][3] += a.z * b.w;
            acc[3][0] += a.w * b.x; acc[3][1] += a.w * b.y; acc[3][2] += a.w * b.z; acc[3][3] += a.w * b.w;
        }
        __syncthreads();
    }

    #pragma unroll
    for (int i = 0; i < 4; i++) {
        int gm = m0 + (ty << 2) + i;
        if (gm < NN) {
            *(float4*)(C + (size_t)gm * DIM + n0 + (tx << 2)) =
                make_float4(acc[i][0], acc[i][1], acc[i][2], acc[i][3]);
        }
    }
}

// ---------------------------------------------------------------------------
// Kernel 2: fused edge pipeline, v3.
// One block = 128 edges (4 nodes) x 4 heads (128 cols), 256 threads,
// 8x8 micro-tile, register-prefetch software pipeline, <=128 regs (2 CTA/SM).
// ---------------------------------------------------------------------------
__global__ __launch_bounds__(256, 2) void edge_kernel(
    const float* __restrict__ ea,
    const int* __restrict__ eidx,       // edge_index row 0 = neighbors (int32)
    const float* __restrict__ WE1,
    const float* __restrict__ WE2,
    const float* __restrict__ bE2,
    float* __restrict__ out)
{
    const int hg2  = blockIdx.x;        // 0..1 -> heads 4*hg2 .. 4*hg2+3
    const int tile = blockIdx.y;        // 0..2499
    const int e0   = tile * 128;
    const int ncol0 = hg2 * 128;

    __shared__ float As[16][132];       // ea chunk [k][edge]
    __shared__ float Bs[16][132];       // WE1 chunk [k][col]
    __shared__ float W2s[16][4];
    __shared__ float sc[4][128];        // scores -> attn (local head, edge)
    __shared__ float e2s[4][128];
    __shared__ int   nb[128];

    const int tid = threadIdx.x;
    const int tx = tid & 15, ty = tid >> 4;   // ty in [0,16)

    if (tid < 128) nb[tid] = eidx[e0 + tid];

    float acc[8][8] = {};
    float e2a0 = 0.f, e2a1 = 0.f;
    const int e2e = tid & 127;
    const int e2hb = (tid >> 7) << 1;          // local head base: 0 or 2

    // indices for the tile loads (same every iteration)
    const int ar0 = tid >> 2;                  // ea row for l=0
    const int ac0 = (tid & 3) << 2;            // ea col-in-chunk for l=0
    const int ar1 = (tid + 256) >> 2;
    const int ac1 = ((tid + 256) & 3) << 2;
    const int br0 = tid >> 5, bc0 = (tid & 31) << 2;
    const int br1 = (tid + 256) >> 5, bc1 = ((tid + 256) & 31) << 2;

    // ---- prologue: prefetch tile 0 ----------------------------------------
    float4 pa0 = *(const float4*)(ea + (size_t)(e0 + ar0) * DIM + ac0);
    float4 pa1 = *(const float4*)(ea + (size_t)(e0 + ar1) * DIM + ac1);
    float4 pb0 = *(const float4*)(WE1 + (size_t)br0 * DIM + ncol0 + bc0);
    float4 pb1 = *(const float4*)(WE1 + (size_t)br1 * DIM + ncol0 + bc1);
    float w2p = 0.f;
    if (tid < 64) w2p = WE2[(tid >> 2) * NHEADS + hg2 * 4 + (tid & 3)];

    for (int k0 = 0; k0 < DIM; k0 += 16) {
        // store prefetched tile into smem (As transposed)
        As[ac0 + 0][ar0] = pa0.x; As[ac0 + 1][ar0] = pa0.y;
        As[ac0 + 2][ar0] = pa0.z; As[ac0 + 3][ar0] = pa0.w;
        As[ac1 + 0][ar1] = pa1.x; As[ac1 + 1][ar1] = pa1.y;
        As[ac1 + 2][ar1] = pa1.z; As[ac1 + 3][ar1] = pa1.w;
        *(float4*)&Bs[br0][bc0] = pb0;
        *(float4*)&Bs[br1][bc1] = pb1;
        if (tid < 64) W2s[tid >> 2][tid & 3] = w2p;
        __syncthreads();

        // prefetch next tile (overlaps with compute below)
        int k0n = k0 + 16;
        if (k0n < DIM) {
            pa0 = *(const float4*)(ea + (size_t)(e0 + ar0) * DIM + k0n + ac0);
            pa1 = *(const float4*)(ea + (size_t)(e0 + ar1) * DIM + k0n + ac1);
            pb0 = *(const float4*)(WE1 + (size_t)(k0n + br0) * DIM + ncol0 + bc0);
            pb1 = *(const float4*)(WE1 + (size_t)(k0n + br1) * DIM + ncol0 + bc1);
            if (tid < 64) w2p = WE2[(k0n + (tid >> 2)) * NHEADS + hg2 * 4 + (tid & 3)];
        }

        #pragma unroll
        for (int k = 0; k < 16; k++) {
            float a[8], b[8];
            *(float4*)&a[0] = *(float4*)&As[k][ty << 3];
            *(float4*)&a[4] = *(float4*)&As[k][(ty << 3) + 4];
            *(float4*)&b[0] = *(float4*)&Bs[k][tx << 2];
            *(float4*)&b[4] = *(float4*)&Bs[k][64 + (tx << 2)];
            #pragma unroll
            for (int r = 0; r < 8; r++)
                #pragma unroll
                for (int j = 0; j < 8; j++)
                    acc[r][j] += a[r] * b[j];
            // fused E2: edge = tid&127, two local heads e2hb, e2hb+1
            float ae = As[k][e2e];
            e2a0 += ae * W2s[k][e2hb];
            e2a1 += ae * W2s[k][e2hb + 1];
        }
        __syncthreads();
    }

    e2s[e2hb][e2e]     = e2a0 + bE2[hg2 * 4 + e2hb];
    e2s[e2hb + 1][e2e] = e2a1 + bE2[hg2 * 4 + e2hb + 1];
    __syncthreads();

    // ---- Phase 2: scores --------------------------------------------------
    // Thread rows: e = ty*8 + r (all in one node: e>>5 == ty>>2).
    // Group A cols ncol0 + tx*4 (local head tx>>3), group B cols +64
    // (local head 2 + (tx>>3)). Reduce over the 8-lane tx octet.
    const int node = tile * 4 + (ty >> 2);
    const float4 q4a = *(const float4*)(g_Q + (size_t)node * DIM + ncol0 + (tx << 2));
    const float4 q4b = *(const float4*)(g_Q + (size_t)node * DIM + ncol0 + 64 + (tx << 2));
    const int hA = tx >> 3;

    #pragma unroll
    for (int r = 0; r < 8; r++) {
        int e = (ty << 3) + r;
        int m = nb[e];
        float4 k4a = *(const float4*)(g_K + (size_t)m * DIM + ncol0 + (tx << 2));
        float4 k4b = *(const float4*)(g_K + (size_t)m * DIM + ncol0 + 64 + (tx << 2));
        float p0 = acc[r][0] * k4a.x * q4a.x + acc[r][1] * k4a.y * q4a.y
                 + acc[r][2] * k4a.z * q4a.z + acc[r][3] * k4a.w * q4a.w;
        float p1 = acc[r][4] * k4b.x * q4b.x + acc[r][5] * k4b.y * q4b.y
                 + acc[r][6] * k4b.z * q4b.z + acc[r][7] * k4b.w * q4b.w;
        #pragma unroll
        for (int o = 1; o < 8; o <<= 1) {
            p0 += __shfl_xor_sync(0xffffffffu, p0, o);
            p1 += __shfl_xor_sync(0xffffffffu, p1, o);
        }
        if ((tx & 7) == 0) {
            float s0 = p0 + e2s[hA][e];
            float s1 = p1 + e2s[2 + hA][e];
            sc[hA][e]     = fminf(fmaxf(s0, -8.f), 8.f);
            sc[2 + hA][e] = fminf(fmaxf(s1, -8.f), 8.f);
        }
    }
    __syncthreads();

    // ---- Phase 3: softmax over deg=32 per (node, local head) -------------
    // Iteration it: thread handles head (tid>>7) + 2*it, edge tid&127.
    // Warp = 32 consecutive tids -> one node's 32 edges, one head.
    {
        #pragma unroll
        for (int it = 0; it < 2; it++) {
            int h = (tid >> 7) + 2 * it;
            int e = tid & 127;
            float s = sc[h][e];
            float mx = s;
            #pragma unroll
            for (int o = 16; o; o >>= 1) mx = fmaxf(mx, __shfl_xor_sync(0xffffffffu, mx, o));
            float p = __expf(s - mx);
            float sum = p;
            #pragma unroll
            for (int o = 16; o; o >>= 1) sum += __shfl_xor_sync(0xffffffffu, sum, o);
            sc[h][e] = p / sum;                // warp-local rewrite, safe
        }
    }
    __syncthreads();

    // ---- Phase 4: output -------------------------------------------------
    // Thread covers (local node i = tid>>6, cols c and c+64 with c = tid&63).
    {
        const int i = tid >> 6;
        const int c = tid & 63;
        const int h0 = c >> 5;             // local head of col c   (0..1)
        const int h1 = 2 + h0;             // local head of col c+64
        float acc0 = 0.f, acc1 = 0.f;
        #pragma unroll 8
        for (int d = 0; d < 32; d++) {
            int e = i * 32 + d;
            const float* vr = g_V + (size_t)nb[e] * DIM + ncol0 + c;
            acc0 += sc[h0][e] * vr[0];
            acc1 += sc[h1][e] * vr[64];
        }
        size_t row = (size_t)(tile * 4 + i) * DIM + ncol0;
        out[row + c]      = acc0;
        out[row + c + 64] = acc1;
    }
}

// ---------------------------------------------------------------------------
extern "C" void kernel_launch(void* const* d_in, const int* in_sizes, int n_in,
                              void* d_out, int out_size)
{
    const float* x   = (const float*)d_in[0];
    const int*   ei  = (const int*)d_in[1];     // int32 (JAX x64 disabled)
    const float* ea  = (const float*)d_in[2];
    const float* WQ  = (const float*)d_in[3];
    const float* WK  = (const float*)d_in[4];
    const float* WV  = (const float*)d_in[5];
    const float* WE1 = (const float*)d_in[6];
    const float* WE2 = (const float*)d_in[7];
    const float* bE2 = (const float*)d_in[8];
    float* out = (float*)d_out;

    qkv_kernel<<<dim3((NN + 63) / 64, DIM / 64, 3), 256>>>(x, WQ, WK, WV);
    edge_kernel<<<dim3(2, NE / 128), 256>>>(ea, ei, WE1, WE2, bE2, out);
}

// round 13
// speedup vs baseline: 2.0768x; 1.2850x over previous
#include <cuda_runtime.h>
#include <cuda_bf16.h>
#include <cstdint>

#define NN   10000
#define DEG  32
#define DIM  256
#define NHEADS 8
#define NE   (NN*DEG)

// Scratch (no cudaMalloc allowed)
__device__ float g_Q[NN * DIM];
__device__ float g_K[NN * DIM];
__device__ float g_V[NN * DIM];
__device__ __nv_bfloat16 g_W1t_hi[DIM * DIM];   // WE1^T bf16 hi  [n][k]
__device__ __nv_bfloat16 g_W1t_lo[DIM * DIM];   // WE1^T bf16 lo  [n][k]

// ---------------------------------------------------------------------------
// smem layout for edge_kernel (dynamic, 82432 B)
// ---------------------------------------------------------------------------
#define APAD      72                      // bf16 row stride for MMA tiles
#define TILE_B    (128 * APAD * 2)        // 18432 B per tile
#define A_HI_OFF  0
#define A_LO_OFF  (A_HI_OFF + TILE_B)
#define B_HI_OFF  (A_LO_OFF + TILE_B)
#define B_LO_OFF  (B_HI_OFF + TILE_B)
#define E1_OFF    0                       // reuses tile region after GEMM
#define E1_STRIDE 129                     // floats; conflict-free column reads
#define PERS_OFF  (B_LO_OFF + TILE_B)     // 73728
#define SC_OFF    PERS_OFF                // float sc[4][128]
#define E2_OFF    (SC_OFF + 2048)         // float e2s[4][128]
#define NB_OFF    (E2_OFF + 2048)         // int nb[128]
#define W2_OFF    (NB_OFF + 512)          // float W2s[256][4]
#define SMEM_TOTAL (W2_OFF + 4096)        // 82432

__device__ __forceinline__ uint32_t smem_u32(const void* p) {
    uint32_t a;
    asm("{ .reg .u64 t; cvta.to.shared.u64 t, %1; cvt.u32.u64 %0, t; }" : "=r"(a) : "l"(p));
    return a;
}

#define LDM4(r, a) \
    asm volatile("ldmatrix.sync.aligned.m8n8.x4.shared.b16 {%0,%1,%2,%3}, [%4];" \
        : "=r"((r)[0]), "=r"((r)[1]), "=r"((r)[2]), "=r"((r)[3]) : "r"(a))

#define MMA16816(d, a, b0_, b1_) \
    asm volatile("mma.sync.aligned.m16n8k16.row.col.f32.bf16.bf16.f32 " \
        "{%0,%1,%2,%3}, {%4,%5,%6,%7}, {%8,%9}, {%0,%1,%2,%3};" \
        : "+f"((d)[0]), "+f"((d)[1]), "+f"((d)[2]), "+f"((d)[3]) \
        : "r"((a)[0]), "r"((a)[1]), "r"((a)[2]), "r"((a)[3]), "r"(b0_), "r"(b1_))

// ---------------------------------------------------------------------------
// prep_kernel: WE1^T split to bf16 hi/lo.
// ---------------------------------------------------------------------------
__global__ void prep_kernel(const float* __restrict__ WE1) {
    int n = blockIdx.x, k = threadIdx.x;
    float v = WE1[(size_t)k * DIM + n];
    __nv_bfloat16 h = __float2bfloat16(v);
    g_W1t_hi[(size_t)n * DIM + k] = h;
    g_W1t_lo[(size_t)n * DIM + k] = __float2bfloat16(v - __bfloat162float(h));
}

// ---------------------------------------------------------------------------
// Kernel 1: Q/K/V projections (R4 known-good).
// ---------------------------------------------------------------------------
__global__ __launch_bounds__(256) void qkv_kernel(
    const float* __restrict__ x,
    const float* __restrict__ WQ,
    const float* __restrict__ WK,
    const float* __restrict__ WV)
{
    const float* W = (blockIdx.z == 0) ? WQ : (blockIdx.z == 1) ? WK : WV;
    float* C       = (blockIdx.z == 0) ? g_Q : (blockIdx.z == 1) ? g_K : g_V;

    __shared__ float As[16][68];
    __shared__ float Bs[16][68];

    const int tid = threadIdx.x;
    const int tx = tid & 15, ty = tid >> 4;
    const int m0 = blockIdx.x * 64, n0 = blockIdx.y * 64;

    float acc[4][4] = {};

    for (int k0 = 0; k0 < DIM; k0 += 16) {
        {
            int r = tid >> 2, c = (tid & 3) << 2;
            float4 v = make_float4(0.f, 0.f, 0.f, 0.f);
            int gm = m0 + r;
            if (gm < NN) v = *(const float4*)(x + (size_t)gm * DIM + k0 + c);
            As[c + 0][r] = v.x; As[c + 1][r] = v.y;
            As[c + 2][r] = v.z; As[c + 3][r] = v.w;
        }
        {
            int wr = tid >> 4, wc = (tid & 15) << 2;
            *(float4*)&Bs[wr][wc] = *(const float4*)(W + (size_t)(k0 + wr) * DIM + n0 + wc);
        }
        __syncthreads();

        #pragma unroll
        for (int k = 0; k < 16; k++) {
            float4 a = *(float4*)&As[k][ty << 2];
            float4 b = *(float4*)&Bs[k][tx << 2];
            acc[0][0] += a.x * b.x; acc[0][1] += a.x * b.y; acc[0][2] += a.x * b.z; acc[0][3] += a.x * b.w;
            acc[1][0] += a.y * b.x; acc[1][1] += a.y * b.y; acc[1][2] += a.y * b.z; acc[1][3] += a.y * b.w;
            acc[2][0] += a.z * b.x; acc[2][1] += a.z * b.y; acc[2][2] += a.z * b.z; acc[2][3] += a.z * b.w;
            acc[3][0] += a.w * b.x; acc[3][1] += a.w * b.y; acc[3][2] += a.w * b.z; acc[3][3] += a.w * b.w;
        }
        __syncthreads();
    }

    #pragma unroll
    for (int i = 0; i < 4; i++) {
        int gm = m0 + (ty << 2) + i;
        if (gm < NN)
            *(float4*)(C + (size_t)gm * DIM + n0 + (tx << 2)) =
                make_float4(acc[i][0], acc[i][1], acc[i][2], acc[i][3]);
    }
}

// ---------------------------------------------------------------------------
// Kernel 2: fused edge pipeline, warp-MMA bf16x3-split E1 GEMM.
// Block = 128 edges (4 nodes) x 128 cols (4 heads), 256 threads, 8 warps.
// Warp (wr = w&3, wc = w>>2) computes 32x64 of E1.  K in 4 chunks of 64.
// ---------------------------------------------------------------------------
__global__ __launch_bounds__(256, 2) void edge_kernel(
    const float* __restrict__ ea,
    const int* __restrict__ eidx,
    const float* __restrict__ WE2,
    const float* __restrict__ bE2,
    float* __restrict__ out)
{
    extern __shared__ __align__(16) uint8_t dyn[];

    const int hg2  = blockIdx.x;            // 0..1 -> heads 4*hg2..+3
    const int tile = blockIdx.y;            // 0..2499
    const int e0   = tile * 128;
    const int ncol0 = hg2 * 128;

    float* E1s        = (float*)(dyn + E1_OFF);
    float (*sc)[128]  = (float(*)[128])(dyn + SC_OFF);
    float (*e2s)[128] = (float(*)[128])(dyn + E2_OFF);
    int*   nb         = (int*)(dyn + NB_OFF);
    float (*W2s)[4]   = (float(*)[4])(dyn + W2_OFF);

    const int tid  = threadIdx.x;
    const int w    = tid >> 5, lane = tid & 31;
    const int wr   = w & 3, wc = w >> 2;
    const uint32_t sbase = smem_u32(dyn);

    // ---- init: nb + W2s ---------------------------------------------------
    if (tid < 128) nb[tid] = eidx[e0 + tid];
    *(float4*)W2s[tid] = *(const float4*)(WE2 + (size_t)tid * NHEADS + hg2 * 4);
    __syncthreads();

    // ---- MMA lane address constants ---------------------------------------
    // A frag (m16k16): matrices [m0k0, m8k0, m0k8, m8k8] by lane octet
    const uint32_t a_lane = 2u * (((lane & 7) + 8 * ((lane >> 3) & 1)) * APAD + 8 * (lane >> 4));
    // B frag (n16k16): matrices [n0k0, n0k8, n8k0, n8k8]
    const uint32_t b_lane = 2u * (((lane & 7) + 8 * (lane >> 4)) * APAD + 8 * ((lane >> 3) & 1));
    const uint32_t Ah_base = sbase + A_HI_OFF + 2u * (wr * 32 * APAD) + a_lane;
    const uint32_t Al_base = sbase + A_LO_OFF + 2u * (wr * 32 * APAD) + a_lane;
    const uint32_t Bh_base = sbase + B_HI_OFF + 2u * (wc * 64 * APAD) + b_lane;
    const uint32_t Bl_base = sbase + B_LO_OFF + 2u * (wc * 64 * APAD) + b_lane;

    float acc[2][8][4] = {};
    float e2a[4] = {0.f, 0.f, 0.f, 0.f};

    const int arow = tid >> 1, ahalf = tid & 1;      // A-load mapping

    for (int kc = 0; kc < 4; kc++) {
        // ---- load/convert A (ea -> bf16 hi/lo) + fused E2 ------------------
        {
            const float4* ap = (const float4*)(ea + (size_t)(e0 + arow) * DIM + kc * 64 + ahalf * 32);
            uint8_t* ahp = dyn + A_HI_OFF + (arow * APAD + ahalf * 32) * 2;
            uint8_t* alp = dyn + A_LO_OFF + (arow * APAD + ahalf * 32) * 2;
            #pragma unroll
            for (int i = 0; i < 8; i++) {
                float4 v = ap[i];
                __nv_bfloat162 h01 = __floats2bfloat162_rn(v.x, v.y);
                __nv_bfloat162 h23 = __floats2bfloat162_rn(v.z, v.w);
                float l0 = v.x - __bfloat162float(h01.x);
                float l1 = v.y - __bfloat162float(h01.y);
                float l2 = v.z - __bfloat162float(h23.x);
                float l3 = v.w - __bfloat162float(h23.y);
                __nv_bfloat162 q01 = __floats2bfloat162_rn(l0, l1);
                __nv_bfloat162 q23 = __floats2bfloat162_rn(l2, l3);
                *(uint2*)(ahp + i * 8) = make_uint2(*(uint32_t*)&h01, *(uint32_t*)&h23);
                *(uint2*)(alp + i * 8) = make_uint2(*(uint32_t*)&q01, *(uint32_t*)&q23);
                int kg = kc * 64 + ahalf * 32 + i * 4;
                #pragma unroll
                for (int h = 0; h < 4; h++)
                    e2a[h] += v.x * W2s[kg][h]     + v.y * W2s[kg + 1][h]
                            + v.z * W2s[kg + 2][h] + v.w * W2s[kg + 3][h];
            }
        }
        // ---- load B (bf16 hi/lo from global) -------------------------------
        {
            #pragma unroll
            for (int l = 0; l < 4; l++) {
                int idx = tid + l * 256;
                int n = idx >> 3, q = idx & 7;
                const uint4* sh = (const uint4*)(g_W1t_hi + (size_t)(ncol0 + n) * DIM + kc * 64);
                const uint4* sl = (const uint4*)(g_W1t_lo + (size_t)(ncol0 + n) * DIM + kc * 64);
                *(uint4*)(dyn + B_HI_OFF + n * (APAD * 2) + q * 16) = sh[q];
                *(uint4*)(dyn + B_LO_OFF + n * (APAD * 2) + q * 16) = sl[q];
            }
        }
        __syncthreads();

        // ---- warp MMA: 32x64 per warp, 3-term split ------------------------
        #pragma unroll
        for (int kt = 0; kt < 4; kt++) {
            const uint32_t koff = 2u * (kt * 16);
            uint32_t ah[2][4], al[2][4];
            LDM4(ah[0], Ah_base + koff);
            LDM4(ah[1], Ah_base + 2u * (16 * APAD) + koff);
            LDM4(al[0], Al_base + koff);
            LDM4(al[1], Al_base + 2u * (16 * APAD) + koff);
            #pragma unroll
            for (int ng = 0; ng < 4; ng++) {
                uint32_t bh[4], bl[4];
                LDM4(bh, Bh_base + 2u * (ng * 16 * APAD) + koff);
                LDM4(bl, Bl_base + 2u * (ng * 16 * APAD) + koff);
                #pragma unroll
                for (int mt = 0; mt < 2; mt++) {
                    #pragma unroll
                    for (int ntp = 0; ntp < 2; ntp++) {
                        float* d = acc[mt][2 * ng + ntp];
                        MMA16816(d, ah[mt], bh[2 * ntp], bh[2 * ntp + 1]);
                        MMA16816(d, al[mt], bh[2 * ntp], bh[2 * ntp + 1]);
                        MMA16816(d, ah[mt], bl[2 * ntp], bl[2 * ntp + 1]);
                    }
                }
            }
        }
        __syncthreads();
    }

    // ---- E2 finalize (pairs combine via shuffle) ---------------------------
    {
        #pragma unroll
        for (int h = 0; h < 4; h++)
            e2a[h] += __shfl_xor_sync(0xffffffffu, e2a[h], 1);
        if (ahalf == 0) {
            #pragma unroll
            for (int h = 0; h < 4; h++)
                e2s[h][arow] = e2a[h] + bE2[hg2 * 4 + h];
        }
    }

    // ---- stage E1 acc -> smem (overwrites tile region) ---------------------
    {
        const int r0 = wr * 32 + (lane >> 2);
        const int c0 = wc * 64 + 2 * (lane & 3);
        #pragma unroll
        for (int mt = 0; mt < 2; mt++) {
            #pragma unroll
            for (int nt = 0; nt < 8; nt++) {
                int row = r0 + mt * 16;
                int col = c0 + nt * 8;
                E1s[row * E1_STRIDE + col]           = acc[mt][nt][0];
                E1s[row * E1_STRIDE + col + 1]       = acc[mt][nt][1];
                E1s[(row + 8) * E1_STRIDE + col]     = acc[mt][nt][2];
                E1s[(row + 8) * E1_STRIDE + col + 1] = acc[mt][nt][3];
            }
        }
    }
    __syncthreads();

    // ---- Phase 2: scores --------------------------------------------------
    // warp w: sp = w&3 (edges sp*32+lane), ch = w>>2 (col half -> heads 2ch, 2ch+1)
    {
        const int sp = w & 3, ch = w >> 2;
        const int e = sp * 32 + lane;
        const int node = tile * 4 + sp;
        const int m = nb[e];
        const float* er = E1s + e * E1_STRIDE + ch * 64;
        const float* kr = g_K + (size_t)m * DIM + ncol0 + ch * 64;
        const float* qr = g_Q + (size_t)node * DIM + ncol0 + ch * 64;
        float s0 = 0.f, s1 = 0.f;
        #pragma unroll
        for (int j = 0; j < 8; j++) {
            float4 kv = ((const float4*)kr)[j];
            float4 qv = ((const float4*)qr)[j];
            s0 += er[j * 4 + 0] * kv.x * qv.x + er[j * 4 + 1] * kv.y * qv.y
                + er[j * 4 + 2] * kv.z * qv.z + er[j * 4 + 3] * kv.w * qv.w;
            float4 kw = ((const float4*)(kr + 32))[j];
            float4 qw = ((const float4*)(qr + 32))[j];
            s1 += er[32 + j * 4 + 0] * kw.x * qw.x + er[32 + j * 4 + 1] * kw.y * qw.y
                + er[32 + j * 4 + 2] * kw.z * qw.z + er[32 + j * 4 + 3] * kw.w * qw.w;
        }
        s0 += e2s[2 * ch][e];
        s1 += e2s[2 * ch + 1][e];
        sc[2 * ch][e]     = fminf(fmaxf(s0, -8.f), 8.f);
        sc[2 * ch + 1][e] = fminf(fmaxf(s1, -8.f), 8.f);
    }
    __syncthreads();

    // ---- Phase 3: softmax over deg=32 per (node, local head) --------------
    {
        #pragma unroll
        for (int it = 0; it < 2; it++) {
            int h = (tid >> 7) + 2 * it;
            int e = tid & 127;
            float s = sc[h][e];
            float mx = s;
            #pragma unroll
            for (int o = 16; o; o >>= 1) mx = fmaxf(mx, __shfl_xor_sync(0xffffffffu, mx, o));
            float p = __expf(s - mx);
            float sum = p;
            #pragma unroll
            for (int o = 16; o; o >>= 1) sum += __shfl_xor_sync(0xffffffffu, sum, o);
            sc[h][e] = p / sum;
        }
    }
    __syncthreads();

    // ---- Phase 4: output ---------------------------------------------------
    {
        const int i = tid >> 6;
        const int c = tid & 63;
        const int h0 = c >> 5;
        const int h1 = 2 + h0;
        float acc0 = 0.f, acc1 = 0.f;
        #pragma unroll 8
        for (int d = 0; d < 32; d++) {
            int e = i * 32 + d;
            const float* vr = g_V + (size_t)nb[e] * DIM + ncol0 + c;
            acc0 += sc[h0][e] * vr[0];
            acc1 += sc[h1][e] * vr[64];
        }
        size_t row = (size_t)(tile * 4 + i) * DIM + ncol0;
        out[row + c]      = acc0;
        out[row + c + 64] = acc1;
    }
}

// ---------------------------------------------------------------------------
extern "C" void kernel_launch(void* const* d_in, const int* in_sizes, int n_in,
                              void* d_out, int out_size)
{
    const float* x   = (const float*)d_in[0];
    const int*   ei  = (const int*)d_in[1];     // int32 (JAX x64 disabled)
    const float* ea  = (const float*)d_in[2];
    const float* WQ  = (const float*)d_in[3];
    const float* WK  = (const float*)d_in[4];
    const float* WV  = (const float*)d_in[5];
    const float* WE1 = (const float*)d_in[6];
    const float* WE2 = (const float*)d_in[7];
    const float* bE2 = (const float*)d_in[8];
    float* out = (float*)d_out;

    static bool attr_done = false;
    if (!attr_done) {
        cudaFuncSetAttribute(edge_kernel,
                             cudaFuncAttributeMaxDynamicSharedMemorySize, SMEM_TOTAL);
        attr_done = true;
    }

    prep_kernel<<<DIM, DIM>>>(WE1);
    qkv_kernel<<<dim3((NN + 63) / 64, DIM / 64, 3), 256>>>(x, WQ, WK, WV);
    edge_kernel<<<dim3(2, NE / 128), 256, SMEM_TOTAL>>>(ea, ei, WE2, bE2, out);
}

// round 14
// speedup vs baseline: 2.3843x; 1.1481x over previous
#include <cuda_runtime.h>
#include <cuda_bf16.h>
#include <cstdint>

#define NN   10000
#define NNP  10112                        // NN padded to 128
#define DEG  32
#define DIM  256
#define NHEADS 8
#define NE   (NN*DEG)

// Scratch (no cudaMalloc allowed)
__device__ float g_Q[NN * DIM];
__device__ float g_K[NN * DIM];
__device__ float g_V[NN * DIM];
__device__ __nv_bfloat16 g_W1t_hi[DIM * DIM];   // WE1^T bf16 hi  [n][k]
__device__ __nv_bfloat16 g_W1t_lo[DIM * DIM];
__device__ __nv_bfloat16 g_Wqt_hi[DIM * DIM];   // WQ^T
__device__ __nv_bfloat16 g_Wqt_lo[DIM * DIM];
__device__ __nv_bfloat16 g_Wkt_hi[DIM * DIM];   // WK^T
__device__ __nv_bfloat16 g_Wkt_lo[DIM * DIM];
__device__ __nv_bfloat16 g_Wvt_hi[DIM * DIM];   // WV^T
__device__ __nv_bfloat16 g_Wvt_lo[DIM * DIM];
__device__ __nv_bfloat16 g_x_hi[NNP * DIM];     // x bf16 hi (rows >= NN zero)
__device__ __nv_bfloat16 g_x_lo[NNP * DIM];

// ---------------------------------------------------------------------------
// smem layout (dynamic).  MMA tiles: bf16, row stride APAD.
// ---------------------------------------------------------------------------
#define APAD      72
#define TILE_B    (128 * APAD * 2)        // 18432 B
#define A_HI_OFF  0
#define A_LO_OFF  (A_HI_OFF + TILE_B)
#define B_HI_OFF  (A_LO_OFF + TILE_B)
#define B_LO_OFF  (B_HI_OFF + TILE_B)
#define E1_OFF    0
#define E1_STRIDE 129
#define PERS_OFF  (B_LO_OFF + TILE_B)     // 73728
#define SC_OFF    PERS_OFF
#define E2_OFF    (SC_OFF + 2048)
#define NB_OFF    (E2_OFF + 2048)
#define W2_OFF    (NB_OFF + 512)
#define SMEM_EDGE (W2_OFF + 4096)         // 82432
#define SMEM_QKV  (B_LO_OFF + TILE_B)     // 73728

__device__ __forceinline__ uint32_t smem_u32(const void* p) {
    uint32_t a;
    asm("{ .reg .u64 t; cvta.to.shared.u64 t, %1; cvt.u32.u64 %0, t; }" : "=r"(a) : "l"(p));
    return a;
}

#define LDM4(r, a) \
    asm volatile("ldmatrix.sync.aligned.m8n8.x4.shared.b16 {%0,%1,%2,%3}, [%4];" \
        : "=r"((r)[0]), "=r"((r)[1]), "=r"((r)[2]), "=r"((r)[3]) : "r"(a))

#define MMA16816(d, a, b0_, b1_) \
    asm volatile("mma.sync.aligned.m16n8k16.row.col.f32.bf16.bf16.f32 " \
        "{%0,%1,%2,%3}, {%4,%5,%6,%7}, {%8,%9}, {%0,%1,%2,%3};" \
        : "+f"((d)[0]), "+f"((d)[1]), "+f"((d)[2]), "+f"((d)[3]) \
        : "r"((a)[0]), "r"((a)[1]), "r"((a)[2]), "r"((a)[3]), "r"(b0_), "r"(b1_))

#define CP16(dst, src) \
    asm volatile("cp.async.cg.shared.global [%0], [%1], 16;" :: "r"(dst), "l"(src))
#define CP_COMMIT()  asm volatile("cp.async.commit_group;" ::: "memory")
#define CP_WAIT0()   asm volatile("cp.async.wait_group 0;" ::: "memory")

// ---------------------------------------------------------------------------
// prep_w: split WE1^T, WQ^T, WK^T, WV^T into bf16 hi/lo.  <<<256, 256>>>
// ---------------------------------------------------------------------------
__global__ void prep_w(const float* __restrict__ WE1, const float* __restrict__ WQ,
                       const float* __restrict__ WK,  const float* __restrict__ WV)
{
    int n = blockIdx.x, k = threadIdx.x;
    size_t src = (size_t)k * DIM + n;
    size_t dst = (size_t)n * DIM + k;
    float v;
    __nv_bfloat16 h;
    v = WE1[src]; h = __float2bfloat16(v);
    g_W1t_hi[dst] = h; g_W1t_lo[dst] = __float2bfloat16(v - __bfloat162float(h));
    v = WQ[src];  h = __float2bfloat16(v);
    g_Wqt_hi[dst] = h; g_Wqt_lo[dst] = __float2bfloat16(v - __bfloat162float(h));
    v = WK[src];  h = __float2bfloat16(v);
    g_Wkt_hi[dst] = h; g_Wkt_lo[dst] = __float2bfloat16(v - __bfloat162float(h));
    v = WV[src];  h = __float2bfloat16(v);
    g_Wvt_hi[dst] = h; g_Wvt_lo[dst] = __float2bfloat16(v - __bfloat162float(h));
}

// ---------------------------------------------------------------------------
// prep_x: split x into bf16 hi/lo, zero-pad rows NN..NNP.  <<<NNP, 256>>>
// ---------------------------------------------------------------------------
__global__ void prep_x(const float* __restrict__ x)
{
    int row = blockIdx.x, k = threadIdx.x;
    float v = (row < NN) ? x[(size_t)row * DIM + k] : 0.f;
    __nv_bfloat16 h = __float2bfloat16(v);
    g_x_hi[(size_t)row * DIM + k] = h;
    g_x_lo[(size_t)row * DIM + k] = __float2bfloat16(v - __bfloat162float(h));
}

// ---------------------------------------------------------------------------
// Kernel 1: Q/K/V projections via warp-MMA bf16x3 split.
// Block = 128 rows x 128 cols, 256 thr, grid (79, 2, 3).
// ---------------------------------------------------------------------------
__global__ __launch_bounds__(256, 2) void qkv_kernel()
{
    extern __shared__ __align__(16) uint8_t dyn[];

    const __nv_bfloat16 *Bh, *Bl;
    float* C;
    if (blockIdx.z == 0)      { Bh = g_Wqt_hi; Bl = g_Wqt_lo; C = g_Q; }
    else if (blockIdx.z == 1) { Bh = g_Wkt_hi; Bl = g_Wkt_lo; C = g_K; }
    else                      { Bh = g_Wvt_hi; Bl = g_Wvt_lo; C = g_V; }

    const int m0 = blockIdx.x * 128, n0 = blockIdx.y * 128;
    const int tid = threadIdx.x;
    const int w = tid >> 5, lane = tid & 31;
    const int wr = w & 3, wc = w >> 2;
    const uint32_t sbase = smem_u32(dyn);

    const uint32_t a_lane = 2u * (((lane & 7) + 8 * ((lane >> 3) & 1)) * APAD + 8 * (lane >> 4));
    const uint32_t b_lane = 2u * (((lane & 7) + 8 * (lane >> 4)) * APAD + 8 * ((lane >> 3) & 1));
    const uint32_t Ah_base = sbase + A_HI_OFF + 2u * (wr * 32 * APAD) + a_lane;
    const uint32_t Al_base = sbase + A_LO_OFF + 2u * (wr * 32 * APAD) + a_lane;
    const uint32_t Bh_base = sbase + B_HI_OFF + 2u * (wc * 64 * APAD) + b_lane;
    const uint32_t Bl_base = sbase + B_LO_OFF + 2u * (wc * 64 * APAD) + b_lane;

    float acc[2][8][4] = {};

    for (int kc = 0; kc < 4; kc++) {
        #pragma unroll
        for (int l = 0; l < 4; l++) {
            int idx = tid + l * 256;
            int r = idx >> 3, q = idx & 7;
            uint32_t soff = (uint32_t)(r * (APAD * 2) + q * 16);
            size_t goff = (size_t)(m0 + r) * DIM + kc * 64 + q * 8;
            CP16(sbase + A_HI_OFF + soff, g_x_hi + goff);
            CP16(sbase + A_LO_OFF + soff, g_x_lo + goff);
            size_t boff = (size_t)(n0 + r) * DIM + kc * 64 + q * 8;
            CP16(sbase + B_HI_OFF + soff, Bh + boff);
            CP16(sbase + B_LO_OFF + soff, Bl + boff);
        }
        CP_COMMIT();
        CP_WAIT0();
        __syncthreads();

        #pragma unroll
        for (int kt = 0; kt < 4; kt++) {
            const uint32_t koff = 2u * (kt * 16);
            uint32_t ah[2][4], al[2][4];
            LDM4(ah[0], Ah_base + koff);
            LDM4(ah[1], Ah_base + 2u * (16 * APAD) + koff);
            LDM4(al[0], Al_base + koff);
            LDM4(al[1], Al_base + 2u * (16 * APAD) + koff);
            #pragma unroll
            for (int ng = 0; ng < 4; ng++) {
                uint32_t bh[4], bl[4];
                LDM4(bh, Bh_base + 2u * (ng * 16 * APAD) + koff);
                LDM4(bl, Bl_base + 2u * (ng * 16 * APAD) + koff);
                #pragma unroll
                for (int mt = 0; mt < 2; mt++) {
                    #pragma unroll
                    for (int ntp = 0; ntp < 2; ntp++) {
                        float* d = acc[mt][2 * ng + ntp];
                        MMA16816(d, ah[mt], bh[2 * ntp], bh[2 * ntp + 1]);
                        MMA16816(d, al[mt], bh[2 * ntp], bh[2 * ntp + 1]);
                        MMA16816(d, ah[mt], bl[2 * ntp], bl[2 * ntp + 1]);
                    }
                }
            }
        }
        __syncthreads();
    }

    // epilogue: direct global stores (guarded)
    {
        const int r0 = wr * 32 + (lane >> 2);
        const int c0 = n0 + wc * 64 + 2 * (lane & 3);
        #pragma unroll
        for (int mt = 0; mt < 2; mt++) {
            #pragma unroll
            for (int nt = 0; nt < 8; nt++) {
                int row = m0 + r0 + mt * 16;
                int col = c0 + nt * 8;
                if (row < NN) {
                    C[(size_t)row * DIM + col]     = acc[mt][nt][0];
                    C[(size_t)row * DIM + col + 1] = acc[mt][nt][1];
                }
                if (row + 8 < NN) {
                    C[(size_t)(row + 8) * DIM + col]     = acc[mt][nt][2];
                    C[(size_t)(row + 8) * DIM + col + 1] = acc[mt][nt][3];
                }
            }
        }
    }
}

// ---------------------------------------------------------------------------
// Kernel 2: fused edge pipeline, warp-MMA bf16x3-split E1 GEMM (R13 core)
// + cp.async B loads overlapped with A convert.
// ---------------------------------------------------------------------------
__global__ __launch_bounds__(256, 2) void edge_kernel(
    const float* __restrict__ ea,
    const int* __restrict__ eidx,
    const float* __restrict__ WE2,
    const float* __restrict__ bE2,
    float* __restrict__ out)
{
    extern __shared__ __align__(16) uint8_t dyn[];

    const int hg2  = blockIdx.x;
    const int tile = blockIdx.y;
    const int e0   = tile * 128;
    const int ncol0 = hg2 * 128;

    float* E1s        = (float*)(dyn + E1_OFF);
    float (*sc)[128]  = (float(*)[128])(dyn + SC_OFF);
    float (*e2s)[128] = (float(*)[128])(dyn + E2_OFF);
    int*   nb         = (int*)(dyn + NB_OFF);
    float (*W2s)[4]   = (float(*)[4])(dyn + W2_OFF);

    const int tid  = threadIdx.x;
    const int w    = tid >> 5, lane = tid & 31;
    const int wr   = w & 3, wc = w >> 2;
    const uint32_t sbase = smem_u32(dyn);

    if (tid < 128) nb[tid] = eidx[e0 + tid];
    *(float4*)W2s[tid] = *(const float4*)(WE2 + (size_t)tid * NHEADS + hg2 * 4);
    __syncthreads();

    const uint32_t a_lane = 2u * (((lane & 7) + 8 * ((lane >> 3) & 1)) * APAD + 8 * (lane >> 4));
    const uint32_t b_lane = 2u * (((lane & 7) + 8 * (lane >> 4)) * APAD + 8 * ((lane >> 3) & 1));
    const uint32_t Ah_base = sbase + A_HI_OFF + 2u * (wr * 32 * APAD) + a_lane;
    const uint32_t Al_base = sbase + A_LO_OFF + 2u * (wr * 32 * APAD) + a_lane;
    const uint32_t Bh_base = sbase + B_HI_OFF + 2u * (wc * 64 * APAD) + b_lane;
    const uint32_t Bl_base = sbase + B_LO_OFF + 2u * (wc * 64 * APAD) + b_lane;

    float acc[2][8][4] = {};
    float e2a[4] = {0.f, 0.f, 0.f, 0.f};

    const int arow = tid >> 1, ahalf = tid & 1;

    for (int kc = 0; kc < 4; kc++) {
        // ---- B loads: cp.async (overlaps with A convert below) -------------
        {
            #pragma unroll
            for (int l = 0; l < 4; l++) {
                int idx = tid + l * 256;
                int n = idx >> 3, q = idx & 7;
                uint32_t soff = (uint32_t)(n * (APAD * 2) + q * 16);
                size_t goff = (size_t)(ncol0 + n) * DIM + kc * 64 + q * 8;
                CP16(sbase + B_HI_OFF + soff, g_W1t_hi + goff);
                CP16(sbase + B_LO_OFF + soff, g_W1t_lo + goff);
            }
            CP_COMMIT();
        }
        // ---- A convert (ea fp32 -> bf16 hi/lo) + fused E2 ------------------
        {
            const float4* ap = (const float4*)(ea + (size_t)(e0 + arow) * DIM + kc * 64 + ahalf * 32);
            uint8_t* ahp = dyn + A_HI_OFF + (arow * APAD + ahalf * 32) * 2;
            uint8_t* alp = dyn + A_LO_OFF + (arow * APAD + ahalf * 32) * 2;
            #pragma unroll
            for (int i = 0; i < 8; i++) {
                float4 v = ap[i];
                __nv_bfloat162 h01 = __floats2bfloat162_rn(v.x, v.y);
                __nv_bfloat162 h23 = __floats2bfloat162_rn(v.z, v.w);
                float l0 = v.x - __bfloat162float(h01.x);
                float l1 = v.y - __bfloat162float(h01.y);
                float l2 = v.z - __bfloat162float(h23.x);
                float l3 = v.w - __bfloat162float(h23.y);
                __nv_bfloat162 q01 = __floats2bfloat162_rn(l0, l1);
                __nv_bfloat162 q23 = __floats2bfloat162_rn(l2, l3);
                *(uint2*)(ahp + i * 8) = make_uint2(*(uint32_t*)&h01, *(uint32_t*)&h23);
                *(uint2*)(alp + i * 8) = make_uint2(*(uint32_t*)&q01, *(uint32_t*)&q23);
                int kg = kc * 64 + ahalf * 32 + i * 4;
                #pragma unroll
                for (int h = 0; h < 4; h++)
                    e2a[h] += v.x * W2s[kg][h]     + v.y * W2s[kg + 1][h]
                            + v.z * W2s[kg + 2][h] + v.w * W2s[kg + 3][h];
            }
        }
        CP_WAIT0();
        __syncthreads();

        // ---- warp MMA: 32x64 per warp, 3-term split ------------------------
        #pragma unroll
        for (int kt = 0; kt < 4; kt++) {
            const uint32_t koff = 2u * (kt * 16);
            uint32_t ah[2][4], al[2][4];
            LDM4(ah[0], Ah_base + koff);
            LDM4(ah[1], Ah_base + 2u * (16 * APAD) + koff);
            LDM4(al[0], Al_base + koff);
            LDM4(al[1], Al_base + 2u * (16 * APAD) + koff);
            #pragma unroll
            for (int ng = 0; ng < 4; ng++) {
                uint32_t bh[4], bl[4];
                LDM4(bh, Bh_base + 2u * (ng * 16 * APAD) + koff);
                LDM4(bl, Bl_base + 2u * (ng * 16 * APAD) + koff);
                #pragma unroll
                for (int mt = 0; mt < 2; mt++) {
                    #pragma unroll
                    for (int ntp = 0; ntp < 2; ntp++) {
                        float* d = acc[mt][2 * ng + ntp];
                        MMA16816(d, ah[mt], bh[2 * ntp], bh[2 * ntp + 1]);
                        MMA16816(d, al[mt], bh[2 * ntp], bh[2 * ntp + 1]);
                        MMA16816(d, ah[mt], bl[2 * ntp], bl[2 * ntp + 1]);
                    }
                }
            }
        }
        __syncthreads();
    }

    // ---- E2 finalize -------------------------------------------------------
    {
        #pragma unroll
        for (int h = 0; h < 4; h++)
            e2a[h] += __shfl_xor_sync(0xffffffffu, e2a[h], 1);
        if (ahalf == 0) {
            #pragma unroll
            for (int h = 0; h < 4; h++)
                e2s[h][arow] = e2a[h] + bE2[hg2 * 4 + h];
        }
    }

    // ---- stage E1 acc -> smem ---------------------------------------------
    {
        const int r0 = wr * 32 + (lane >> 2);
        const int c0 = wc * 64 + 2 * (lane & 3);
        #pragma unroll
        for (int mt = 0; mt < 2; mt++) {
            #pragma unroll
            for (int nt = 0; nt < 8; nt++) {
                int row = r0 + mt * 16;
                int col = c0 + nt * 8;
                E1s[row * E1_STRIDE + col]           = acc[mt][nt][0];
                E1s[row * E1_STRIDE + col + 1]       = acc[mt][nt][1];
                E1s[(row + 8) * E1_STRIDE + col]     = acc[mt][nt][2];
                E1s[(row + 8) * E1_STRIDE + col + 1] = acc[mt][nt][3];
            }
        }
    }
    __syncthreads();

    // ---- Phase 2: scores ---------------------------------------------------
    {
        const int sp = w & 3, ch = w >> 2;
        const int e = sp * 32 + lane;
        const int node = tile * 4 + sp;
        const int m = nb[e];
        const float* er = E1s + e * E1_STRIDE + ch * 64;
        const float* kr = g_K + (size_t)m * DIM + ncol0 + ch * 64;
        const float* qr = g_Q + (size_t)node * DIM + ncol0 + ch * 64;
        float s0 = 0.f, s1 = 0.f;
        #pragma unroll
        for (int j = 0; j < 8; j++) {
            float4 kv = ((const float4*)kr)[j];
            float4 qv = ((const float4*)qr)[j];
            s0 += er[j * 4 + 0] * kv.x * qv.x + er[j * 4 + 1] * kv.y * qv.y
                + er[j * 4 + 2] * kv.z * qv.z + er[j * 4 + 3] * kv.w * qv.w;
            float4 kw = ((const float4*)(kr + 32))[j];
            float4 qw = ((const float4*)(qr + 32))[j];
            s1 += er[32 + j * 4 + 0] * kw.x * qw.x + er[32 + j * 4 + 1] * kw.y * qw.y
                + er[32 + j * 4 + 2] * kw.z * qw.z + er[32 + j * 4 + 3] * kw.w * qw.w;
        }
        s0 += e2s[2 * ch][e];
        s1 += e2s[2 * ch + 1][e];
        sc[2 * ch][e]     = fminf(fmaxf(s0, -8.f), 8.f);
        sc[2 * ch + 1][e] = fminf(fmaxf(s1, -8.f), 8.f);
    }
    __syncthreads();

    // ---- Phase 3: softmax --------------------------------------------------
    {
        #pragma unroll
        for (int it = 0; it < 2; it++) {
            int h = (tid >> 7) + 2 * it;
            int e = tid & 127;
            float s = sc[h][e];
            float mx = s;
            #pragma unroll
            for (int o = 16; o; o >>= 1) mx = fmaxf(mx, __shfl_xor_sync(0xffffffffu, mx, o));
            float p = __expf(s - mx);
            float sum = p;
            #pragma unroll
            for (int o = 16; o; o >>= 1) sum += __shfl_xor_sync(0xffffffffu, sum, o);
            sc[h][e] = p / sum;
        }
    }
    __syncthreads();

    // ---- Phase 4: output ---------------------------------------------------
    {
        const int i = tid >> 6;
        const int c = tid & 63;
        const int h0 = c >> 5;
        const int h1 = 2 + h0;
        float acc0 = 0.f, acc1 = 0.f;
        #pragma unroll 8
        for (int d = 0; d < 32; d++) {
            int e = i * 32 + d;
            const float* vr = g_V + (size_t)nb[e] * DIM + ncol0 + c;
            acc0 += sc[h0][e] * vr[0];
            acc1 += sc[h1][e] * vr[64];
        }
        size_t row = (size_t)(tile * 4 + i) * DIM + ncol0;
        out[row + c]      = acc0;
        out[row + c + 64] = acc1;
    }
}

// ---------------------------------------------------------------------------
extern "C" void kernel_launch(void* const* d_in, const int* in_sizes, int n_in,
                              void* d_out, int out_size)
{
    const float* x   = (const float*)d_in[0];
    const int*   ei  = (const int*)d_in[1];     // int32 (JAX x64 disabled)
    const float* ea  = (const float*)d_in[2];
    const float* WQ  = (const float*)d_in[3];
    const float* WK  = (const float*)d_in[4];
    const float* WV  = (const float*)d_in[5];
    const float* WE1 = (const float*)d_in[6];
    const float* WE2 = (const float*)d_in[7];
    const float* bE2 = (const float*)d_in[8];
    float* out = (float*)d_out;

    static bool attr_done = false;
    if (!attr_done) {
        cudaFuncSetAttribute(edge_kernel,
                             cudaFuncAttributeMaxDynamicSharedMemorySize, SMEM_EDGE);
        cudaFuncSetAttribute(qkv_kernel,
                             cudaFuncAttributeMaxDynamicSharedMemorySize, SMEM_QKV);
        attr_done = true;
    }

    prep_w<<<DIM, DIM>>>(WE1, WQ, WK, WV);
    prep_x<<<NNP, DIM>>>(x);
    qkv_kernel<<<dim3(NNP / 128, 2, 3), 256, SMEM_QKV>>>();
    edge_kernel<<<dim3(2, NE / 128), 256, SMEM_EDGE>>>(ea, ei, WE2, bE2, out);
}

// round 15
// speedup vs baseline: 2.5677x; 1.0769x over previous
#include <cuda_runtime.h>
#include <cuda_bf16.h>
#include <cstdint>

#define NN   10000
#define NNP  10112                        // NN padded to 128
#define DEG  32
#define DIM  256
#define NHEADS 8
#define NE   (NN*DEG)

// Scratch (no cudaMalloc allowed)
__device__ float g_Q[NN * DIM];
__device__ float g_K[NN * DIM];
__device__ float g_V[NN * DIM];
__device__ __nv_bfloat16 g_W1t_hi[DIM * DIM];   // WE1^T bf16 hi  [n][k]
__device__ __nv_bfloat16 g_W1t_lo[DIM * DIM];
__device__ __nv_bfloat16 g_Wqt_hi[DIM * DIM];
__device__ __nv_bfloat16 g_Wqt_lo[DIM * DIM];
__device__ __nv_bfloat16 g_Wkt_hi[DIM * DIM];
__device__ __nv_bfloat16 g_Wkt_lo[DIM * DIM];
__device__ __nv_bfloat16 g_Wvt_hi[DIM * DIM];
__device__ __nv_bfloat16 g_Wvt_lo[DIM * DIM];
__device__ __nv_bfloat16 g_x_hi[NNP * DIM];
__device__ __nv_bfloat16 g_x_lo[NNP * DIM];

// ---------------------------------------------------------------------------
// common helpers
// ---------------------------------------------------------------------------
#define APAD      72                      // bf16 row stride (144 B)

__device__ __forceinline__ uint32_t smem_u32(const void* p) {
    uint32_t a;
    asm("{ .reg .u64 t; cvta.to.shared.u64 t, %1; cvt.u32.u64 %0, t; }" : "=r"(a) : "l"(p));
    return a;
}

#define LDM4(r, a) \
    asm volatile("ldmatrix.sync.aligned.m8n8.x4.shared.b16 {%0,%1,%2,%3}, [%4];" \
        : "=r"((r)[0]), "=r"((r)[1]), "=r"((r)[2]), "=r"((r)[3]) : "r"(a))

#define MMA16816(d, a, b0_, b1_) \
    asm volatile("mma.sync.aligned.m16n8k16.row.col.f32.bf16.bf16.f32 " \
        "{%0,%1,%2,%3}, {%4,%5,%6,%7}, {%8,%9}, {%0,%1,%2,%3};" \
        : "+f"((d)[0]), "+f"((d)[1]), "+f"((d)[2]), "+f"((d)[3]) \
        : "r"((a)[0]), "r"((a)[1]), "r"((a)[2]), "r"((a)[3]), "r"(b0_), "r"(b1_))

#define CP16(dst, src) \
    asm volatile("cp.async.cg.shared.global [%0], [%1], 16;" :: "r"(dst), "l"(src))
#define CP_COMMIT()  asm volatile("cp.async.commit_group;" ::: "memory")
#define CP_WAIT0()   asm volatile("cp.async.wait_group 0;" ::: "memory")

// ---------------------------------------------------------------------------
// qkv smem layout (R14, unchanged)
// ---------------------------------------------------------------------------
#define QTILE_B   (128 * APAD * 2)        // 18432
#define QA_HI     0
#define QA_LO     (QA_HI + QTILE_B)
#define QB_HI     (QA_LO + QTILE_B)
#define QB_LO     (QB_HI + QTILE_B)
#define SMEM_QKV  (QB_LO + QTILE_B)       // 73728

// ---------------------------------------------------------------------------
// edge smem layout (v2): block = 128 edges x 256 cols
// ---------------------------------------------------------------------------
#define EA_HI     0                       // 128 x APAD bf16 = 18432
#define EA_LO     (EA_HI + 18432)
#define EB_HI     (EA_LO + 18432)         // 256 x APAD bf16 = 36864
#define EB_LO     (EB_HI + 36864)
// E1 staging reuses [0, 133120) after GEMM
#define E1_STRIDE 260                     // floats (65 16B-granules, odd)
#define EPERS     133120
#define ESC_OFF   EPERS                   // float sc[8][128]  = 4096
#define EE2_OFF   (EPERS + 4096)          // float e2s[8][128] = 4096
#define ENB_OFF   (EPERS + 8192)          // int nb[128]       = 512
#define EW2_OFF   (EPERS + 8704)          // float W2s[256][8] = 8192
#define SMEM_EDGE (EPERS + 16896)         // 150016

// ---------------------------------------------------------------------------
// prep_w: split WE1^T, WQ^T, WK^T, WV^T into bf16 hi/lo.  <<<256, 256>>>
// ---------------------------------------------------------------------------
__global__ void prep_w(const float* __restrict__ WE1, const float* __restrict__ WQ,
                       const float* __restrict__ WK,  const float* __restrict__ WV)
{
    int n = blockIdx.x, k = threadIdx.x;
    size_t src = (size_t)k * DIM + n;
    size_t dst = (size_t)n * DIM + k;
    float v;
    __nv_bfloat16 h;
    v = WE1[src]; h = __float2bfloat16(v);
    g_W1t_hi[dst] = h; g_W1t_lo[dst] = __float2bfloat16(v - __bfloat162float(h));
    v = WQ[src];  h = __float2bfloat16(v);
    g_Wqt_hi[dst] = h; g_Wqt_lo[dst] = __float2bfloat16(v - __bfloat162float(h));
    v = WK[src];  h = __float2bfloat16(v);
    g_Wkt_hi[dst] = h; g_Wkt_lo[dst] = __float2bfloat16(v - __bfloat162float(h));
    v = WV[src];  h = __float2bfloat16(v);
    g_Wvt_hi[dst] = h; g_Wvt_lo[dst] = __float2bfloat16(v - __bfloat162float(h));
}

// ---------------------------------------------------------------------------
// prep_x: split x into bf16 hi/lo, zero-pad rows NN..NNP.  <<<NNP, 256>>>
// ---------------------------------------------------------------------------
__global__ void prep_x(const float* __restrict__ x)
{
    int row = blockIdx.x, k = threadIdx.x;
    float v = (row < NN) ? x[(size_t)row * DIM + k] : 0.f;
    __nv_bfloat16 h = __float2bfloat16(v);
    g_x_hi[(size_t)row * DIM + k] = h;
    g_x_lo[(size_t)row * DIM + k] = __float2bfloat16(v - __bfloat162float(h));
}

// ---------------------------------------------------------------------------
// Kernel 1: Q/K/V projections via warp-MMA bf16x3 split (R14, unchanged).
// ---------------------------------------------------------------------------
__global__ __launch_bounds__(256, 2) void qkv_kernel()
{
    extern __shared__ __align__(16) uint8_t dyn[];

    const __nv_bfloat16 *Bh, *Bl;
    float* C;
    if (blockIdx.z == 0)      { Bh = g_Wqt_hi; Bl = g_Wqt_lo; C = g_Q; }
    else if (blockIdx.z == 1) { Bh = g_Wkt_hi; Bl = g_Wkt_lo; C = g_K; }
    else                      { Bh = g_Wvt_hi; Bl = g_Wvt_lo; C = g_V; }

    const int m0 = blockIdx.x * 128, n0 = blockIdx.y * 128;
    const int tid = threadIdx.x;
    const int w = tid >> 5, lane = tid & 31;
    const int wr = w & 3, wc = w >> 2;
    const uint32_t sbase = smem_u32(dyn);

    const uint32_t a_lane = 2u * (((lane & 7) + 8 * ((lane >> 3) & 1)) * APAD + 8 * (lane >> 4));
    const uint32_t b_lane = 2u * (((lane & 7) + 8 * (lane >> 4)) * APAD + 8 * ((lane >> 3) & 1));
    const uint32_t Ah_base = sbase + QA_HI + 2u * (wr * 32 * APAD) + a_lane;
    const uint32_t Al_base = sbase + QA_LO + 2u * (wr * 32 * APAD) + a_lane;
    const uint32_t Bh_base = sbase + QB_HI + 2u * (wc * 64 * APAD) + b_lane;
    const uint32_t Bl_base = sbase + QB_LO + 2u * (wc * 64 * APAD) + b_lane;

    float acc[2][8][4] = {};

    for (int kc = 0; kc < 4; kc++) {
        #pragma unroll
        for (int l = 0; l < 4; l++) {
            int idx = tid + l * 256;
            int r = idx >> 3, q = idx & 7;
            uint32_t soff = (uint32_t)(r * (APAD * 2) + q * 16);
            size_t goff = (size_t)(m0 + r) * DIM + kc * 64 + q * 8;
            CP16(sbase + QA_HI + soff, g_x_hi + goff);
            CP16(sbase + QA_LO + soff, g_x_lo + goff);
            size_t boff = (size_t)(n0 + r) * DIM + kc * 64 + q * 8;
            CP16(sbase + QB_HI + soff, Bh + boff);
            CP16(sbase + QB_LO + soff, Bl + boff);
        }
        CP_COMMIT();
        CP_WAIT0();
        __syncthreads();

        #pragma unroll
        for (int kt = 0; kt < 4; kt++) {
            const uint32_t koff = 2u * (kt * 16);
            uint32_t ah[2][4], al[2][4];
            LDM4(ah[0], Ah_base + koff);
            LDM4(ah[1], Ah_base + 2u * (16 * APAD) + koff);
            LDM4(al[0], Al_base + koff);
            LDM4(al[1], Al_base + 2u * (16 * APAD) + koff);
            #pragma unroll
            for (int ng = 0; ng < 4; ng++) {
                uint32_t bh[4], bl[4];
                LDM4(bh, Bh_base + 2u * (ng * 16 * APAD) + koff);
                LDM4(bl, Bl_base + 2u * (ng * 16 * APAD) + koff);
                #pragma unroll
                for (int mt = 0; mt < 2; mt++) {
                    #pragma unroll
                    for (int ntp = 0; ntp < 2; ntp++) {
                        float* d = acc[mt][2 * ng + ntp];
                        MMA16816(d, ah[mt], bh[2 * ntp], bh[2 * ntp + 1]);
                        MMA16816(d, al[mt], bh[2 * ntp], bh[2 * ntp + 1]);
                        MMA16816(d, ah[mt], bl[2 * ntp], bl[2 * ntp + 1]);
                    }
                }
            }
        }
        __syncthreads();
    }

    {
        const int r0 = wr * 32 + (lane >> 2);
        const int c0 = n0 + wc * 64 + 2 * (lane & 3);
        #pragma unroll
        for (int mt = 0; mt < 2; mt++) {
            #pragma unroll
            for (int nt = 0; nt < 8; nt++) {
                int row = m0 + r0 + mt * 16;
                int col = c0 + nt * 8;
                if (row < NN) {
                    C[(size_t)row * DIM + col]     = acc[mt][nt][0];
                    C[(size_t)row * DIM + col + 1] = acc[mt][nt][1];
                }
                if (row + 8 < NN) {
                    C[(size_t)(row + 8) * DIM + col]     = acc[mt][nt][2];
                    C[(size_t)(row + 8) * DIM + col + 1] = acc[mt][nt][3];
                }
            }
        }
    }
}

// ---------------------------------------------------------------------------
// Kernel 2: fused edge pipeline v2.
// Block = 128 edges (4 nodes) x 256 cols (ALL 8 heads), 256 thr, 8 warps.
// Warp tile 64x64 (wr = w&1, wc = w>>1).  K in 4 chunks of 64.
// Term-major MMA order; A LDGs prefetched under MMA; B via cp.async.
// 1 CTA/SM (smem 146.5 KB), __launch_bounds__(256,1) -> 256 regs.
// ---------------------------------------------------------------------------
__global__ __launch_bounds__(256, 1) void edge_kernel(
    const float* __restrict__ ea,
    const int* __restrict__ eidx,
    const float* __restrict__ WE2,
    const float* __restrict__ bE2,
    float* __restrict__ out)
{
    extern __shared__ __align__(16) uint8_t dyn[];

    const int tile = blockIdx.x;            // 0..2499
    const int e0   = tile * 128;

    float* E1s        = (float*)(dyn);
    float (*sc)[128]  = (float(*)[128])(dyn + ESC_OFF);
    float (*e2s)[128] = (float(*)[128])(dyn + EE2_OFF);
    int*   nb         = (int*)(dyn + ENB_OFF);
    float (*W2s)[8]   = (float(*)[8])(dyn + EW2_OFF);

    const int tid  = threadIdx.x;
    const int w    = tid >> 5, lane = tid & 31;
    const int wr   = w & 1, wc = w >> 1;
    const uint32_t sbase = smem_u32(dyn);

    if (tid < 128) nb[tid] = eidx[e0 + tid];
    *(float4*)&W2s[tid][0] = *(const float4*)(WE2 + (size_t)tid * NHEADS);
    *(float4*)&W2s[tid][4] = *(const float4*)(WE2 + (size_t)tid * NHEADS + 4);
    __syncthreads();

    const uint32_t a_lane = 2u * (((lane & 7) + 8 * ((lane >> 3) & 1)) * APAD + 8 * (lane >> 4));
    const uint32_t b_lane = 2u * (((lane & 7) + 8 * (lane >> 4)) * APAD + 8 * ((lane >> 3) & 1));
    const uint32_t Ah_base = sbase + EA_HI + 2u * (wr * 64 * APAD) + a_lane;
    const uint32_t Al_base = sbase + EA_LO + 2u * (wr * 64 * APAD) + a_lane;
    const uint32_t Bh_base = sbase + EB_HI + 2u * (wc * 64 * APAD) + b_lane;
    const uint32_t Bl_base = sbase + EB_LO + 2u * (wc * 64 * APAD) + b_lane;

    float acc[4][8][4] = {};
    float e2a[8] = {};
    float4 pv[8];

    const int arow = tid >> 1, ahalf = tid & 1;

    // ---- helpers as lambdas ------------------------------------------------
    auto loadA = [&](int kc) {
        const float4* ap = (const float4*)(ea + (size_t)(e0 + arow) * DIM + kc * 64 + ahalf * 32);
        #pragma unroll
        for (int i = 0; i < 8; i++) pv[i] = ap[i];
    };
    auto asyncB = [&](int kc) {
        #pragma unroll
        for (int l = 0; l < 8; l++) {
            int idx = tid + l * 256;
            int n = idx >> 3, q = idx & 7;
            uint32_t soff = (uint32_t)(n * (APAD * 2) + q * 16);
            size_t goff = (size_t)n * DIM + kc * 64 + q * 8;
            CP16(sbase + EB_HI + soff, g_W1t_hi + goff);
            CP16(sbase + EB_LO + soff, g_W1t_lo + goff);
        }
        CP_COMMIT();
    };
    auto convertA = [&](int kc) {
        uint8_t* ahp = dyn + EA_HI + (arow * APAD + ahalf * 32) * 2;
        uint8_t* alp = dyn + EA_LO + (arow * APAD + ahalf * 32) * 2;
        #pragma unroll
        for (int i = 0; i < 8; i++) {
            float4 v = pv[i];
            __nv_bfloat162 h01 = __floats2bfloat162_rn(v.x, v.y);
            __nv_bfloat162 h23 = __floats2bfloat162_rn(v.z, v.w);
            float l0 = v.x - __bfloat162float(h01.x);
            float l1 = v.y - __bfloat162float(h01.y);
            float l2 = v.z - __bfloat162float(h23.x);
            float l3 = v.w - __bfloat162float(h23.y);
            __nv_bfloat162 q01 = __floats2bfloat162_rn(l0, l1);
            __nv_bfloat162 q23 = __floats2bfloat162_rn(l2, l3);
            *(uint2*)(ahp + i * 8) = make_uint2(*(uint32_t*)&h01, *(uint32_t*)&h23);
            *(uint2*)(alp + i * 8) = make_uint2(*(uint32_t*)&q01, *(uint32_t*)&q23);
            int kg = kc * 64 + ahalf * 32 + i * 4;
            #pragma unroll
            for (int h = 0; h < 8; h++)
                e2a[h] += v.x * W2s[kg][h]     + v.y * W2s[kg + 1][h]
                        + v.z * W2s[kg + 2][h] + v.w * W2s[kg + 3][h];
        }
    };

    // ---- prologue: chunk 0 -------------------------------------------------
    asyncB(0);
    loadA(0);
    convertA(0);
    CP_WAIT0();
    __syncthreads();

    // ---- main loop ---------------------------------------------------------
    for (int kc = 0; kc < 4; kc++) {
        if (kc < 3) loadA(kc + 1);           // LDGs hidden under MMA below

        #pragma unroll
        for (int kt = 0; kt < 4; kt++) {
            const uint32_t koff = 2u * (kt * 16);
            uint32_t ah[4][4], al[4][4];
            #pragma unroll
            for (int m = 0; m < 4; m++) {
                LDM4(ah[m], Ah_base + 2u * (m * 16 * APAD) + koff);
                LDM4(al[m], Al_base + 2u * (m * 16 * APAD) + koff);
            }
            #pragma unroll
            for (int ng = 0; ng < 4; ng++) {
                uint32_t bh[4], bl[4];
                LDM4(bh, Bh_base + 2u * (ng * 16 * APAD) + koff);
                LDM4(bl, Bl_base + 2u * (ng * 16 * APAD) + koff);
                // term-major: same-acc dependency distance = 8
                #pragma unroll
                for (int m = 0; m < 4; m++) {
                    MMA16816(acc[m][2 * ng],     ah[m], bh[0], bh[1]);
                    MMA16816(acc[m][2 * ng + 1], ah[m], bh[2], bh[3]);
                }
                #pragma unroll
                for (int m = 0; m < 4; m++) {
                    MMA16816(acc[m][2 * ng],     al[m], bh[0], bh[1]);
                    MMA16816(acc[m][2 * ng + 1], al[m], bh[2], bh[3]);
                }
                #pragma unroll
                for (int m = 0; m < 4; m++) {
                    MMA16816(acc[m][2 * ng],     ah[m], bl[0], bl[1]);
                    MMA16816(acc[m][2 * ng + 1], ah[m], bl[2], bl[3]);
                }
            }
        }
        __syncthreads();

        if (kc < 3) {
            asyncB(kc + 1);
            convertA(kc + 1);
            CP_WAIT0();
            __syncthreads();
        }
    }

    // ---- E2 finalize -------------------------------------------------------
    {
        #pragma unroll
        for (int h = 0; h < 8; h++)
            e2a[h] += __shfl_xor_sync(0xffffffffu, e2a[h], 1);
        if (ahalf == 0) {
            #pragma unroll
            for (int h = 0; h < 8; h++)
                e2s[h][arow] = e2a[h] + bE2[h];
        }
    }
    __syncthreads();    // everyone done reading tiles; E1 staging overwrites

    // ---- stage E1 acc -> smem ---------------------------------------------
    {
        const int r0 = wr * 64 + (lane >> 2);
        const int c0 = wc * 64 + 2 * (lane & 3);
        #pragma unroll
        for (int m = 0; m < 4; m++) {
            #pragma unroll
            for (int nt = 0; nt < 8; nt++) {
                int row = r0 + m * 16;
                int col = c0 + nt * 8;
                E1s[row * E1_STRIDE + col]           = acc[m][nt][0];
                E1s[row * E1_STRIDE + col + 1]       = acc[m][nt][1];
                E1s[(row + 8) * E1_STRIDE + col]     = acc[m][nt][2];
                E1s[(row + 8) * E1_STRIDE + col + 1] = acc[m][nt][3];
            }
        }
    }
    __syncthreads();

    // ---- Phase 2: scores ---------------------------------------------------
    // warp w: sp = w&3 (edges sp*32+lane), ch = w>>2 (col half: 128 cols = 4 heads)
    {
        const int sp = w & 3, ch = w >> 2;
        const int e = sp * 32 + lane;
        const int node = tile * 4 + sp;
        const int m = nb[e];
        const float* er = E1s + e * E1_STRIDE + ch * 128;
        const float* kr = g_K + (size_t)m * DIM + ch * 128;
        const float* qr = g_Q + (size_t)node * DIM + ch * 128;
        #pragma unroll
        for (int hh = 0; hh < 4; hh++) {
            float s = 0.f;
            #pragma unroll
            for (int j = 0; j < 8; j++) {
                int o = hh * 32 + j * 4;
                float4 ev = *(const float4*)(er + o);
                float4 kv = *(const float4*)(kr + o);
                float4 qv = *(const float4*)(qr + o);
                s += ev.x * kv.x * qv.x + ev.y * kv.y * qv.y
                   + ev.z * kv.z * qv.z + ev.w * kv.w * qv.w;
            }
            s += e2s[4 * ch + hh][e];
            sc[4 * ch + hh][e] = fminf(fmaxf(s, -8.f), 8.f);
        }
    }
    __syncthreads();

    // ---- Phase 3: softmax over deg=32 per (node, head) ---------------------
    {
        #pragma unroll
        for (int it = 0; it < 4; it++) {
            int h = (tid >> 7) + 2 * it;
            int e = tid & 127;
            float s = sc[h][e];
            float mx = s;
            #pragma unroll
            for (int o = 16; o; o >>= 1) mx = fmaxf(mx, __shfl_xor_sync(0xffffffffu, mx, o));
            float p = __expf(s - mx);
            float sum = p;
            #pragma unroll
            for (int o = 16; o; o >>= 1) sum += __shfl_xor_sync(0xffffffffu, sum, o);
            sc[h][e] = p / sum;
        }
    }
    __syncthreads();

    // ---- Phase 4: output ---------------------------------------------------
    {
        const int i = tid >> 6;
        const int c = tid & 63;
        float a0 = 0.f, a1 = 0.f, a2 = 0.f, a3 = 0.f;
        const int h0 = c >> 5;
        #pragma unroll 8
        for (int d = 0; d < 32; d++) {
            int e = i * 32 + d;
            const float* vr = g_V + (size_t)nb[e] * DIM + c;
            a0 += sc[h0][e]     * vr[0];
            a1 += sc[2 + h0][e] * vr[64];
            a2 += sc[4 + h0][e] * vr[128];
            a3 += sc[6 + h0][e] * vr[192];
        }
        size_t row = (size_t)(tile * 4 + i) * DIM + c;
        out[row]       = a0;
        out[row + 64]  = a1;
        out[row + 128] = a2;
        out[row + 192] = a3;
    }
}

// ---------------------------------------------------------------------------
extern "C" void kernel_launch(void* const* d_in, const int* in_sizes, int n_in,
                              void* d_out, int out_size)
{
    const float* x   = (const float*)d_in[0];
    const int*   ei  = (const int*)d_in[1];     // int32 (JAX x64 disabled)
    const float* ea  = (const float*)d_in[2];
    const float* WQ  = (const float*)d_in[3];
    const float* WK  = (const float*)d_in[4];
    const float* WV  = (const float*)d_in[5];
    const float* WE1 = (const float*)d_in[6];
    const float* WE2 = (const float*)d_in[7];
    const float* bE2 = (const float*)d_in[8];
    float* out = (float*)d_out;

    static bool attr_done = false;
    if (!attr_done) {
        cudaFuncSetAttribute(edge_kernel,
                             cudaFuncAttributeMaxDynamicSharedMemorySize, SMEM_EDGE);
        cudaFuncSetAttribute(qkv_kernel,
                             cudaFuncAttributeMaxDynamicSharedMemorySize, SMEM_QKV);
        attr_done = true;
    }

    prep_w<<<DIM, DIM>>>(WE1, WQ, WK, WV);
    prep_x<<<NNP, DIM>>>(x);
    qkv_kernel<<<dim3(NNP / 128, 2, 3), 256, SMEM_QKV>>>();
    edge_kernel<<<NE / 128, 256, SMEM_EDGE>>>(ea, ei, WE2, bE2, out);
}

// round 16
// speedup vs baseline: 2.6045x; 1.0144x over previous
#include <cuda_runtime.h>
#include <cuda_bf16.h>
#include <cstdint>

#define NN   10000
#define NNP  10112                        // NN padded to 128
#define DEG  32
#define DIM  256
#define NHEADS 8
#define NE   (NN*DEG)

// Scratch (no cudaMalloc allowed)
__device__ float g_Q[NN * DIM];
__device__ float g_K[NN * DIM];
__device__ float g_V[NN * DIM];
__device__ __nv_bfloat16 g_W1t_hi[DIM * DIM];   // WE1^T bf16 hi  [n][k]
__device__ __nv_bfloat16 g_W1t_lo[DIM * DIM];
__device__ __nv_bfloat16 g_Wqt_hi[DIM * DIM];
__device__ __nv_bfloat16 g_Wqt_lo[DIM * DIM];
__device__ __nv_bfloat16 g_Wkt_hi[DIM * DIM];
__device__ __nv_bfloat16 g_Wkt_lo[DIM * DIM];
__device__ __nv_bfloat16 g_Wvt_hi[DIM * DIM];
__device__ __nv_bfloat16 g_Wvt_lo[DIM * DIM];
__device__ __nv_bfloat16 g_x_hi[NNP * DIM];
__device__ __nv_bfloat16 g_x_lo[NNP * DIM];

// ---------------------------------------------------------------------------
// common helpers
// ---------------------------------------------------------------------------
#define APAD      72                      // qkv row stride (bf16)

__device__ __forceinline__ uint32_t smem_u32(const void* p) {
    uint32_t a;
    asm("{ .reg .u64 t; cvta.to.shared.u64 t, %1; cvt.u32.u64 %0, t; }" : "=r"(a) : "l"(p));
    return a;
}

#define LDM4(r, a) \
    asm volatile("ldmatrix.sync.aligned.m8n8.x4.shared.b16 {%0,%1,%2,%3}, [%4];" \
        : "=r"((r)[0]), "=r"((r)[1]), "=r"((r)[2]), "=r"((r)[3]) : "r"(a))

#define MMA16816(d, a, b0_, b1_) \
    asm volatile("mma.sync.aligned.m16n8k16.row.col.f32.bf16.bf16.f32 " \
        "{%0,%1,%2,%3}, {%4,%5,%6,%7}, {%8,%9}, {%0,%1,%2,%3};" \
        : "+f"((d)[0]), "+f"((d)[1]), "+f"((d)[2]), "+f"((d)[3]) \
        : "r"((a)[0]), "r"((a)[1]), "r"((a)[2]), "r"((a)[3]), "r"(b0_), "r"(b1_))

#define CP16(dst, src) \
    asm volatile("cp.async.cg.shared.global [%0], [%1], 16;" :: "r"(dst), "l"(src))
#define CP_COMMIT()  asm volatile("cp.async.commit_group;" ::: "memory")
#define CP_WAIT0()   asm volatile("cp.async.wait_group 0;" ::: "memory")

// ---------------------------------------------------------------------------
// qkv smem layout (unchanged)
// ---------------------------------------------------------------------------
#define QTILE_B   (128 * APAD * 2)
#define QA_HI     0
#define QA_LO     (QA_HI + QTILE_B)
#define QB_HI     (QA_LO + QTILE_B)
#define QB_LO     (QB_HI + QTILE_B)
#define SMEM_QKV  (QB_LO + QTILE_B)       // 73728

// ---------------------------------------------------------------------------
// edge smem layout v3: double-buffered chunk-32 stages.
// Row pitch 80 B (40 bf16): conflict-free ldmatrix (banks r*20 mod 32 distinct).
// ---------------------------------------------------------------------------
#define ECH       32                      // k-chunk
#define ROWB      80                      // bytes per tile row
#define SA_HI     0                       // A hi: 128*80 = 10240
#define SA_LO     10240
#define SB_HI     20480                   // B hi: 256*80 = 20480
#define SB_LO     40960
#define ESTAGE    61440                   // per stage; x2 = 122880
// E1 staging reuses [0, 133120) after GEMM
#define E1_STRIDE 260
#define EPERS     133120
#define ESC_OFF   EPERS                   // float sc[8][128]
#define EE2_OFF   (EPERS + 4096)
#define ENB_OFF   (EPERS + 8192)
#define EW2_OFF   (EPERS + 8704)          // float W2s[256][8]
#define SMEM_EDGE (EPERS + 16896)         // 150016

// ---------------------------------------------------------------------------
// prep_w: split WE1^T, WQ^T, WK^T, WV^T into bf16 hi/lo.  <<<256, 256>>>
// ---------------------------------------------------------------------------
__global__ void prep_w(const float* __restrict__ WE1, const float* __restrict__ WQ,
                       const float* __restrict__ WK,  const float* __restrict__ WV)
{
    int n = blockIdx.x, k = threadIdx.x;
    size_t src = (size_t)k * DIM + n;
    size_t dst = (size_t)n * DIM + k;
    float v;
    __nv_bfloat16 h;
    v = WE1[src]; h = __float2bfloat16(v);
    g_W1t_hi[dst] = h; g_W1t_lo[dst] = __float2bfloat16(v - __bfloat162float(h));
    v = WQ[src];  h = __float2bfloat16(v);
    g_Wqt_hi[dst] = h; g_Wqt_lo[dst] = __float2bfloat16(v - __bfloat162float(h));
    v = WK[src];  h = __float2bfloat16(v);
    g_Wkt_hi[dst] = h; g_Wkt_lo[dst] = __float2bfloat16(v - __bfloat162float(h));
    v = WV[src];  h = __float2bfloat16(v);
    g_Wvt_hi[dst] = h; g_Wvt_lo[dst] = __float2bfloat16(v - __bfloat162float(h));
}

// ---------------------------------------------------------------------------
// prep_x: split x into bf16 hi/lo, zero-pad rows NN..NNP.  <<<NNP, 256>>>
// ---------------------------------------------------------------------------
__global__ void prep_x(const float* __restrict__ x)
{
    int row = blockIdx.x, k = threadIdx.x;
    float v = (row < NN) ? x[(size_t)row * DIM + k] : 0.f;
    __nv_bfloat16 h = __float2bfloat16(v);
    g_x_hi[(size_t)row * DIM + k] = h;
    g_x_lo[(size_t)row * DIM + k] = __float2bfloat16(v - __bfloat162float(h));
}

// ---------------------------------------------------------------------------
// Kernel 1: Q/K/V projections via warp-MMA bf16x3 split (unchanged).
// ---------------------------------------------------------------------------
__global__ __launch_bounds__(256, 2) void qkv_kernel()
{
    extern __shared__ __align__(16) uint8_t dyn[];

    const __nv_bfloat16 *Bh, *Bl;
    float* C;
    if (blockIdx.z == 0)      { Bh = g_Wqt_hi; Bl = g_Wqt_lo; C = g_Q; }
    else if (blockIdx.z == 1) { Bh = g_Wkt_hi; Bl = g_Wkt_lo; C = g_K; }
    else                      { Bh = g_Wvt_hi; Bl = g_Wvt_lo; C = g_V; }

    const int m0 = blockIdx.x * 128, n0 = blockIdx.y * 128;
    const int tid = threadIdx.x;
    const int w = tid >> 5, lane = tid & 31;
    const int wr = w & 3, wc = w >> 2;
    const uint32_t sbase = smem_u32(dyn);

    const uint32_t a_lane = 2u * (((lane & 7) + 8 * ((lane >> 3) & 1)) * APAD + 8 * (lane >> 4));
    const uint32_t b_lane = 2u * (((lane & 7) + 8 * (lane >> 4)) * APAD + 8 * ((lane >> 3) & 1));
    const uint32_t Ah_base = sbase + QA_HI + 2u * (wr * 32 * APAD) + a_lane;
    const uint32_t Al_base = sbase + QA_LO + 2u * (wr * 32 * APAD) + a_lane;
    const uint32_t Bh_base = sbase + QB_HI + 2u * (wc * 64 * APAD) + b_lane;
    const uint32_t Bl_base = sbase + QB_LO + 2u * (wc * 64 * APAD) + b_lane;

    float acc[2][8][4] = {};

    for (int kc = 0; kc < 4; kc++) {
        #pragma unroll
        for (int l = 0; l < 4; l++) {
            int idx = tid + l * 256;
            int r = idx >> 3, q = idx & 7;
            uint32_t soff = (uint32_t)(r * (APAD * 2) + q * 16);
            size_t goff = (size_t)(m0 + r) * DIM + kc * 64 + q * 8;
            CP16(sbase + QA_HI + soff, g_x_hi + goff);
            CP16(sbase + QA_LO + soff, g_x_lo + goff);
            size_t boff = (size_t)(n0 + r) * DIM + kc * 64 + q * 8;
            CP16(sbase + QB_HI + soff, Bh + boff);
            CP16(sbase + QB_LO + soff, Bl + boff);
        }
        CP_COMMIT();
        CP_WAIT0();
        __syncthreads();

        #pragma unroll
        for (int kt = 0; kt < 4; kt++) {
            const uint32_t koff = 2u * (kt * 16);
            uint32_t ah[2][4], al[2][4];
            LDM4(ah[0], Ah_base + koff);
            LDM4(ah[1], Ah_base + 2u * (16 * APAD) + koff);
            LDM4(al[0], Al_base + koff);
            LDM4(al[1], Al_base + 2u * (16 * APAD) + koff);
            #pragma unroll
            for (int ng = 0; ng < 4; ng++) {
                uint32_t bh[4], bl[4];
                LDM4(bh, Bh_base + 2u * (ng * 16 * APAD) + koff);
                LDM4(bl, Bl_base + 2u * (ng * 16 * APAD) + koff);
                #pragma unroll
                for (int mt = 0; mt < 2; mt++) {
                    #pragma unroll
                    for (int ntp = 0; ntp < 2; ntp++) {
                        float* d = acc[mt][2 * ng + ntp];
                        MMA16816(d, ah[mt], bh[2 * ntp], bh[2 * ntp + 1]);
                        MMA16816(d, al[mt], bh[2 * ntp], bh[2 * ntp + 1]);
                        MMA16816(d, ah[mt], bl[2 * ntp], bl[2 * ntp + 1]);
                    }
                }
            }
        }
        __syncthreads();
    }

    {
        const int r0 = wr * 32 + (lane >> 2);
        const int c0 = n0 + wc * 64 + 2 * (lane & 3);
        #pragma unroll
        for (int mt = 0; mt < 2; mt++) {
            #pragma unroll
            for (int nt = 0; nt < 8; nt++) {
                int row = m0 + r0 + mt * 16;
                int col = c0 + nt * 8;
                if (row < NN) {
                    C[(size_t)row * DIM + col]     = acc[mt][nt][0];
                    C[(size_t)row * DIM + col + 1] = acc[mt][nt][1];
                }
                if (row + 8 < NN) {
                    C[(size_t)(row + 8) * DIM + col]     = acc[mt][nt][2];
                    C[(size_t)(row + 8) * DIM + col + 1] = acc[mt][nt][3];
                }
            }
        }
    }
}

// ---------------------------------------------------------------------------
// Kernel 2: fused edge pipeline v3 — double-buffered chunk-32 pipeline.
// Block = 128 edges x 256 cols (all 8 heads), 256 thr, warp tile 64x64.
// loadA/asyncB of chunk k+1 issue BEFORE the MMA of chunk k; convertA after.
// ---------------------------------------------------------------------------
__global__ __launch_bounds__(256, 1) void edge_kernel(
    const float* __restrict__ ea,
    const int* __restrict__ eidx,
    const float* __restrict__ WE2,
    const float* __restrict__ bE2,
    float* __restrict__ out)
{
    extern __shared__ __align__(16) uint8_t dyn[];

    const int tile = blockIdx.x;            // 0..2499
    const int e0   = tile * 128;

    float* E1s        = (float*)(dyn);
    float (*sc)[128]  = (float(*)[128])(dyn + ESC_OFF);
    float (*e2s)[128] = (float(*)[128])(dyn + EE2_OFF);
    int*   nb         = (int*)(dyn + ENB_OFF);
    float (*W2s)[8]   = (float(*)[8])(dyn + EW2_OFF);

    const int tid  = threadIdx.x;
    const int w    = tid >> 5, lane = tid & 31;
    const int wr   = w & 1, wc = w >> 1;
    const uint32_t sbase = smem_u32(dyn);

    if (tid < 128) nb[tid] = eidx[e0 + tid];
    *(float4*)&W2s[tid][0] = *(const float4*)(WE2 + (size_t)tid * NHEADS);
    *(float4*)&W2s[tid][4] = *(const float4*)(WE2 + (size_t)tid * NHEADS + 4);
    __syncthreads();

    // ldmatrix lane addresses for ROWB=80 tiles
    const uint32_t a_lane = ((lane & 7) + 8 * ((lane >> 3) & 1)) * ROWB + (lane >> 4) * 16;
    const uint32_t b_lane = ((lane & 7) + 8 * (lane >> 4)) * ROWB + ((lane >> 3) & 1) * 16;
    const uint32_t AhW = (uint32_t)(wr * 64 * ROWB) + a_lane;   // + SA_HI
    const uint32_t BhW = (uint32_t)(wc * 64 * ROWB) + b_lane;   // + SB_HI

    float acc[4][8][4] = {};
    float e2a[8] = {};
    float4 pv[4];

    const int arow = tid >> 1, ahalf = tid & 1;

    auto loadA = [&](int kc) {
        const float4* ap = (const float4*)(ea + (size_t)(e0 + arow) * DIM + kc * ECH + ahalf * 16);
        #pragma unroll
        for (int i = 0; i < 4; i++) pv[i] = ap[i];
    };
    auto asyncB = [&](int kc, int stg) {
        const uint32_t sb = sbase + stg * ESTAGE;
        #pragma unroll
        for (int l = 0; l < 4; l++) {
            int idx = tid + l * 256;
            int n = idx >> 2, q = idx & 3;
            uint32_t soff = (uint32_t)(n * ROWB + q * 16);
            size_t goff = (size_t)n * DIM + kc * ECH + q * 8;
            CP16(sb + SB_HI + soff, g_W1t_hi + goff);
            CP16(sb + SB_LO + soff, g_W1t_lo + goff);
        }
        CP_COMMIT();
    };
    auto convertA = [&](int kc, int stg) {
        uint8_t* base = dyn + stg * ESTAGE;
        uint8_t* ahp = base + SA_HI + arow * ROWB + ahalf * 32;
        uint8_t* alp = base + SA_LO + arow * ROWB + ahalf * 32;
        #pragma unroll
        for (int i = 0; i < 4; i++) {
            float4 v = pv[i];
            __nv_bfloat162 h01 = __floats2bfloat162_rn(v.x, v.y);
            __nv_bfloat162 h23 = __floats2bfloat162_rn(v.z, v.w);
            float l0 = v.x - __bfloat162float(h01.x);
            float l1 = v.y - __bfloat162float(h01.y);
            float l2 = v.z - __bfloat162float(h23.x);
            float l3 = v.w - __bfloat162float(h23.y);
            __nv_bfloat162 q01 = __floats2bfloat162_rn(l0, l1);
            __nv_bfloat162 q23 = __floats2bfloat162_rn(l2, l3);
            *(uint2*)(ahp + i * 8) = make_uint2(*(uint32_t*)&h01, *(uint32_t*)&h23);
            *(uint2*)(alp + i * 8) = make_uint2(*(uint32_t*)&q01, *(uint32_t*)&q23);
            int kg = kc * ECH + ahalf * 16 + i * 4;
            #pragma unroll
            for (int h = 0; h < 8; h++)
                e2a[h] += v.x * W2s[kg][h]     + v.y * W2s[kg + 1][h]
                        + v.z * W2s[kg + 2][h] + v.w * W2s[kg + 3][h];
        }
    };

    // ---- prologue: fill stage 0 -------------------------------------------
    loadA(0);
    asyncB(0, 0);
    convertA(0, 0);
    CP_WAIT0();
    __syncthreads();

    // ---- pipelined main loop: 8 chunks of 32 ------------------------------
    for (int kc = 0; kc < 8; kc++) {
        const int cur = kc & 1;

        // next chunk's long-latency ops issue before the MMA block
        if (kc < 7) {
            loadA(kc + 1);
            asyncB(kc + 1, cur ^ 1);
        }

        // MMA on current stage (2 k-steps of 16)
        {
            const uint32_t st = sbase + cur * ESTAGE;
            const uint32_t Ah_base = st + SA_HI + AhW;
            const uint32_t Al_base = st + SA_LO + AhW;
            const uint32_t Bh_base = st + SB_HI + BhW;
            const uint32_t Bl_base = st + SB_LO + BhW;
            #pragma unroll
            for (int kt = 0; kt < 2; kt++) {
                const uint32_t koff = (uint32_t)(kt * 32);
                uint32_t ah[4][4], al[4][4];
                #pragma unroll
                for (int m = 0; m < 4; m++) {
                    LDM4(ah[m], Ah_base + (uint32_t)(m * 16 * ROWB) + koff);
                    LDM4(al[m], Al_base + (uint32_t)(m * 16 * ROWB) + koff);
                }
                #pragma unroll
                for (int ng = 0; ng < 4; ng++) {
                    uint32_t bh[4], bl[4];
                    LDM4(bh, Bh_base + (uint32_t)(ng * 16 * ROWB) + koff);
                    LDM4(bl, Bl_base + (uint32_t)(ng * 16 * ROWB) + koff);
                    #pragma unroll
                    for (int m = 0; m < 4; m++) {
                        MMA16816(acc[m][2 * ng],     ah[m], bh[0], bh[1]);
                        MMA16816(acc[m][2 * ng + 1], ah[m], bh[2], bh[3]);
                    }
                    #pragma unroll
                    for (int m = 0; m < 4; m++) {
                        MMA16816(acc[m][2 * ng],     al[m], bh[0], bh[1]);
                        MMA16816(acc[m][2 * ng + 1], al[m], bh[2], bh[3]);
                    }
                    #pragma unroll
                    for (int m = 0; m < 4; m++) {
                        MMA16816(acc[m][2 * ng],     ah[m], bl[0], bl[1]);
                        MMA16816(acc[m][2 * ng + 1], ah[m], bl[2], bl[3]);
                    }
                }
            }
        }

        // convert next chunk's A into the other stage (drains under MMA)
        if (kc < 7) {
            convertA(kc + 1, cur ^ 1);
            CP_WAIT0();
        }
        __syncthreads();
    }

    // ---- E2 finalize -------------------------------------------------------
    {
        #pragma unroll
        for (int h = 0; h < 8; h++)
            e2a[h] += __shfl_xor_sync(0xffffffffu, e2a[h], 1);
        if (ahalf == 0) {
            #pragma unroll
            for (int h = 0; h < 8; h++)
                e2s[h][arow] = e2a[h] + bE2[h];
        }
    }
    __syncthreads();    // all tile reads done; E1 staging overwrites tiles

    // ---- stage E1 acc -> smem ---------------------------------------------
    {
        const int r0 = wr * 64 + (lane >> 2);
        const int c0 = wc * 64 + 2 * (lane & 3);
        #pragma unroll
        for (int m = 0; m < 4; m++) {
            #pragma unroll
            for (int nt = 0; nt < 8; nt++) {
                int row = r0 + m * 16;
                int col = c0 + nt * 8;
                E1s[row * E1_STRIDE + col]           = acc[m][nt][0];
                E1s[row * E1_STRIDE + col + 1]       = acc[m][nt][1];
                E1s[(row + 8) * E1_STRIDE + col]     = acc[m][nt][2];
                E1s[(row + 8) * E1_STRIDE + col + 1] = acc[m][nt][3];
            }
        }
    }
    __syncthreads();

    // ---- Phase 2: scores ---------------------------------------------------
    {
        const int sp = w & 3, ch = w >> 2;
        const int e = sp * 32 + lane;
        const int node = tile * 4 + sp;
        const int m = nb[e];
        const float* er = E1s + e * E1_STRIDE + ch * 128;
        const float* kr = g_K + (size_t)m * DIM + ch * 128;
        const float* qr = g_Q + (size_t)node * DIM + ch * 128;
        #pragma unroll
        for (int hh = 0; hh < 4; hh++) {
            float s = 0.f;
            #pragma unroll
            for (int j = 0; j < 8; j++) {
                int o = hh * 32 + j * 4;
                float4 ev = *(const float4*)(er + o);
                float4 kv = *(const float4*)(kr + o);
                float4 qv = *(const float4*)(qr + o);
                s += ev.x * kv.x * qv.x + ev.y * kv.y * qv.y
                   + ev.z * kv.z * qv.z + ev.w * kv.w * qv.w;
            }
            s += e2s[4 * ch + hh][e];
            sc[4 * ch + hh][e] = fminf(fmaxf(s, -8.f), 8.f);
        }
    }
    __syncthreads();

    // ---- Phase 3: softmax over deg=32 per (node, head) ---------------------
    {
        #pragma unroll
        for (int it = 0; it < 4; it++) {
            int h = (tid >> 7) + 2 * it;
            int e = tid & 127;
            float s = sc[h][e];
            float mx = s;
            #pragma unroll
            for (int o = 16; o; o >>= 1) mx = fmaxf(mx, __shfl_xor_sync(0xffffffffu, mx, o));
            float p = __expf(s - mx);
            float sum = p;
            #pragma unroll
            for (int o = 16; o; o >>= 1) sum += __shfl_xor_sync(0xffffffffu, sum, o);
            sc[h][e] = p / sum;
        }
    }
    __syncthreads();

    // ---- Phase 4: output ---------------------------------------------------
    {
        const int i = tid >> 6;
        const int c = tid & 63;
        float a0 = 0.f, a1 = 0.f, a2 = 0.f, a3 = 0.f;
        const int h0 = c >> 5;
        #pragma unroll 8
        for (int d = 0; d < 32; d++) {
            int e = i * 32 + d;
            const float* vr = g_V + (size_t)nb[e] * DIM + c;
            a0 += sc[h0][e]     * vr[0];
            a1 += sc[2 + h0][e] * vr[64];
            a2 += sc[4 + h0][e] * vr[128];
            a3 += sc[6 + h0][e] * vr[192];
        }
        size_t row = (size_t)(tile * 4 + i) * DIM + c;
        out[row]       = a0;
        out[row + 64]  = a1;
        out[row + 128] = a2;
        out[row + 192] = a3;
    }
}

// ---------------------------------------------------------------------------
extern "C" void kernel_launch(void* const* d_in, const int* in_sizes, int n_in,
                              void* d_out, int out_size)
{
    const float* x   = (const float*)d_in[0];
    const int*   ei  = (const int*)d_in[1];     // int32 (JAX x64 disabled)
    const float* ea  = (const float*)d_in[2];
    const float* WQ  = (const float*)d_in[3];
    const float* WK  = (const float*)d_in[4];
    const float* WV  = (const float*)d_in[5];
    const float* WE1 = (const float*)d_in[6];
    const float* WE2 = (const float*)d_in[7];
    const float* bE2 = (const float*)d_in[8];
    float* out = (float*)d_out;

    static bool attr_done = false;
    if (!attr_done) {
        cudaFuncSetAttribute(edge_kernel,
                             cudaFuncAttributeMaxDynamicSharedMemorySize, SMEM_EDGE);
        cudaFuncSetAttribute(qkv_kernel,
                             cudaFuncAttributeMaxDynamicSharedMemorySize, SMEM_QKV);
        attr_done = true;
    }

    prep_w<<<DIM, DIM>>>(WE1, WQ, WK, WV);
    prep_x<<<NNP, DIM>>>(x);
    qkv_kernel<<<dim3(NNP / 128, 2, 3), 256, SMEM_QKV>>>();
    edge_kernel<<<NE / 128, 256, SMEM_EDGE>>>(ea, ei, WE2, bE2, out);
}